// round 6
// baseline (speedup 1.0000x reference)
#include <cuda_runtime.h>
#include <cuda_bf16.h>
#include <math.h>

// Problem constants
#define Bsz  2
#define Lseq 1024
#define Dm   768
#define NHn  12
#define HDd  64
#define NLn  6
#define MLPd 3072
#define NTOK (Bsz * Lseq)   // 2048

// ---------------------------------------------------------------------------
// Scratch (static device globals; no allocation)
// ---------------------------------------------------------------------------
__device__ float g_x   [NTOK * Dm];
__device__ float g_h   [NTOK * Dm];
__device__ float g_qkv [NTOK * 3 * Dm];
__device__ float g_o   [NTOK * Dm];
__device__ float g_mlp [NTOK * MLPd];
__device__ float g_cond[Bsz * Dm];

// ---------------------------------------------------------------------------
// cond_out[b,n] = ce[b,:] @ cond_w[:,n] + cond_b[n]
// ---------------------------------------------------------------------------
__global__ void cond_kernel(const float* __restrict__ ce,
                            const float* __restrict__ w,
                            const float* __restrict__ cb,
                            float* __restrict__ out) {
    int idx = blockIdx.x * blockDim.x + threadIdx.x;
    if (idx >= Bsz * Dm) return;
    int b = idx / Dm, n = idx % Dm;
    float s = 0.f;
    const float* cer = ce + b * 1536;
    #pragma unroll 4
    for (int k = 0; k < 1536; k++) s += cer[k] * w[k * Dm + n];
    out[idx] = s + cb[n];
}

// ---------------------------------------------------------------------------
// Tiled fp32 GEMM (exact fp32): C = A @ B (+bias +cond +gelu +residual)
// ---------------------------------------------------------------------------
#define GBM 128
#define GBN 128
#define GBK 16

template<bool BIAS, bool GELU_F, bool RES, bool COND>
__global__ __launch_bounds__(256)
void gemm_kernel(const float* __restrict__ A, const float* __restrict__ Bm,
                 const float* __restrict__ bias, const float* __restrict__ res,
                 const float* __restrict__ cond, float* __restrict__ C,
                 int M, int N, int K) {
    __shared__ float As[GBK][GBM + 4];
    __shared__ float Bs[GBK][GBN];

    const int tid = threadIdx.x;
    const int bm = blockIdx.y * GBM;
    const int bn = blockIdx.x * GBN;

    const int tr = (tid / 16) * 8;
    const int tc = (tid % 16) * 8;

    const int arow0 = tid >> 2;
    const int acol4 = (tid & 3) * 4;
    const int brow0 = tid >> 5;
    const int bcol4 = (tid & 31) * 4;

    float acc[8][8];
    #pragma unroll
    for (int i = 0; i < 8; i++)
        #pragma unroll
        for (int j = 0; j < 8; j++) acc[i][j] = 0.f;

    for (int k0 = 0; k0 < K; k0 += GBK) {
        #pragma unroll
        for (int it = 0; it < 2; it++) {
            int r = arow0 + it * 64;
            float4 v = *(const float4*)&A[(size_t)(bm + r) * K + k0 + acol4];
            As[acol4 + 0][r] = v.x;
            As[acol4 + 1][r] = v.y;
            As[acol4 + 2][r] = v.z;
            As[acol4 + 3][r] = v.w;
        }
        #pragma unroll
        for (int it = 0; it < 2; it++) {
            int r = brow0 + it * 8;
            *(float4*)&Bs[r][bcol4] =
                *(const float4*)&Bm[(size_t)(k0 + r) * N + bn + bcol4];
        }
        __syncthreads();

        #pragma unroll
        for (int kk = 0; kk < GBK; kk++) {
            float ra[8], rb[8];
            #pragma unroll
            for (int i = 0; i < 8; i++) ra[i] = As[kk][tr + i];
            #pragma unroll
            for (int j = 0; j < 8; j++) rb[j] = Bs[kk][tc + j];
            #pragma unroll
            for (int i = 0; i < 8; i++)
                #pragma unroll
                for (int j = 0; j < 8; j++) acc[i][j] += ra[i] * rb[j];
        }
        __syncthreads();
    }

    #pragma unroll
    for (int i = 0; i < 8; i++) {
        int row = bm + tr + i;
        #pragma unroll
        for (int j = 0; j < 8; j++) {
            int col = bn + tc + j;
            float v = acc[i][j];
            if (BIAS) v += bias[col];
            if (COND) v += cond[(row / Lseq) * N + col];
            if (GELU_F) v = 0.5f * v * (1.f + erff(v * 0.70710678118654752f));
            if (RES) v += res[(size_t)row * N + col];
            C[(size_t)row * N + col] = v;
        }
    }
}

// ---------------------------------------------------------------------------
// LayerNorm: one block per token row (768 cols), 256 threads x 3 elems
// ---------------------------------------------------------------------------
__global__ __launch_bounds__(256)
void layernorm_kernel(const float* __restrict__ x, const float* __restrict__ g,
                      const float* __restrict__ b, float* __restrict__ out) {
    int row = blockIdx.x;
    int t = threadIdx.x;
    const float* xr = x + (size_t)row * Dm;
    float v0 = xr[t], v1 = xr[t + 256], v2 = xr[t + 512];
    float s = v0 + v1 + v2;
    float q = v0 * v0 + v1 * v1 + v2 * v2;
    #pragma unroll
    for (int o = 16; o > 0; o >>= 1) {
        s += __shfl_xor_sync(0xffffffffu, s, o);
        q += __shfl_xor_sync(0xffffffffu, q, o);
    }
    __shared__ float ss[8], sq[8];
    int wid = t >> 5, lane = t & 31;
    if (!lane) { ss[wid] = s; sq[wid] = q; }
    __syncthreads();
    if (t == 0) {
        float S = 0.f, Q = 0.f;
        #pragma unroll
        for (int i = 0; i < 8; i++) { S += ss[i]; Q += sq[i]; }
        float m = S * (1.f / Dm);
        float var = Q * (1.f / Dm) - m * m;
        ss[0] = m;
        sq[0] = rsqrtf(var + 1e-5f);
    }
    __syncthreads();
    float m = ss[0], r = sq[0];
    float* orow = out + (size_t)row * Dm;
    orow[t]       = (v0 - m) * r * g[t]       + b[t];
    orow[t + 256] = (v1 - m) * r * g[t + 256] + b[t + 256];
    orow[t + 512] = (v2 - m) * r * g[t + 512] + b[t + 512];
}

// ---------------------------------------------------------------------------
// Fused RMSNorm + RoPE on q,k (in place in g_qkv), fp64 transcendentals.
// One block per token (768 threads = 24 warps): warps 0-11 q, 12-23 k.
// Lane p owns head-dim pair (2p, 2p+1). Pairs 0-15 <- x=l%32, 16-31 <- y=l/32,
// omega_j = 10000^(-j/16).
// ---------------------------------------------------------------------------
__global__ __launch_bounds__(768)
void rmsrope_kernel(float* __restrict__ qkv,
                    const float* __restrict__ qs,
                    const float* __restrict__ ks) {
    int token = blockIdx.x;
    int w = threadIdx.x >> 5;
    int lane = threadIdx.x & 31;
    int isK = (w >= NHn);
    int h = isK ? w - NHn : w;
    float* base = qkv + (size_t)token * (3 * Dm) + (isK ? Dm : 0) + h * HDd;
    const float* sc = isK ? ks : qs;

    float x0 = base[2 * lane], x1 = base[2 * lane + 1];
    float s = x0 * x0 + x1 * x1;
    #pragma unroll
    for (int o = 16; o > 0; o >>= 1) s += __shfl_xor_sync(0xffffffffu, s, o);
    float r = rsqrtf(s * (1.f / HDd) + 1e-6f);
    float y0 = x0 * r * sc[2 * lane];
    float y1 = x1 * r * sc[2 * lane + 1];

    int l = token & (Lseq - 1);
    int col = l & 31, rowp = l >> 5;
    double pos, fidx;
    if (lane < 16) { pos = (double)col;  fidx = (double)lane; }
    else           { pos = (double)rowp; fidx = (double)(lane - 16); }
    // omega = 10000^(-fidx/16); angle in double, rounded once to float at use
    double omega = exp(fidx * -0.5756462732485115);
    double ang = pos * omega;
    float c  = (float)cos(ang);
    float sn = (float)sin(ang);
    base[2 * lane]     = c * y0 - sn * y1;
    base[2 * lane + 1] = sn * y0 + c * y1;
}

// ---------------------------------------------------------------------------
// Literal attention: exact 2-pass softmax with true max, score = dot*0.125
// + literal density bias (dscale*density[b,l] + dbias), accurate expf.
// Grid (L/128, NH, B), 128 threads; thread = 1 query. K/V tiles in SMEM.
// ---------------------------------------------------------------------------
__global__ __launch_bounds__(128)
void attn_kernel(const float* __restrict__ qkv, float* __restrict__ o,
                 const float* __restrict__ dens,
                 const float* __restrict__ dscale,
                 const float* __restrict__ dbias, int layer) {
    const int t = threadIdx.x;
    const int h = blockIdx.y;
    const int b = blockIdx.z;
    const int l = blockIdx.x * 128 + t;
    const size_t tokbase = (size_t)(b * Lseq + l) * (3 * Dm);

    float q[HDd];
    const float* qptr = qkv + tokbase + h * HDd;
    #pragma unroll
    for (int d = 0; d < HDd; d++) q[d] = qptr[d];

    const float bias = dscale[layer] * dens[b * Lseq + l] + dbias[layer];

    __shared__ float Ks[64 * 64];
    __shared__ float Vs[64 * 64];

    // Pass 1: exact row max of scores
    float mmax = -1e30f;
    for (int kt = 0; kt < Lseq; kt += 64) {
        __syncthreads();
        #pragma unroll
        for (int i = 0; i < 8; i++) {
            int off = (t + i * 128) * 4;
            int r = off >> 6, d = off & 63;
            const float* kp = qkv + (size_t)(b * Lseq + kt + r) * (3 * Dm)
                                  + Dm + h * HDd + d;
            *(float4*)&Ks[off] = *(const float4*)kp;
        }
        __syncthreads();
        #pragma unroll 2
        for (int j = 0; j < 64; j++) {
            const float* kr = &Ks[j * 64];
            float s = 0.f;
            #pragma unroll
            for (int d = 0; d < HDd; d++) s += q[d] * kr[d];
            s = s * 0.125f + bias;
            mmax = fmaxf(mmax, s);
        }
    }

    // Pass 2: p = expf(s - max); lsum += p; acc += p * v
    float acc[HDd];
    #pragma unroll
    for (int d = 0; d < HDd; d++) acc[d] = 0.f;
    float lsum = 0.f;

    for (int kt = 0; kt < Lseq; kt += 64) {
        __syncthreads();
        #pragma unroll
        for (int i = 0; i < 8; i++) {
            int off = (t + i * 128) * 4;
            int r = off >> 6, d = off & 63;
            const float* kp = qkv + (size_t)(b * Lseq + kt + r) * (3 * Dm)
                                  + Dm + h * HDd + d;
            *(float4*)&Ks[off] = *(const float4*)kp;
            *(float4*)&Vs[off] = *(const float4*)(kp + Dm);
        }
        __syncthreads();
        #pragma unroll 2
        for (int j = 0; j < 64; j++) {
            const float* kr = &Ks[j * 64];
            float s = 0.f;
            #pragma unroll
            for (int d = 0; d < HDd; d++) s += q[d] * kr[d];
            s = s * 0.125f + bias;
            float p = expf(s - mmax);
            lsum += p;
            const float* vr = &Vs[j * 64];
            #pragma unroll
            for (int d = 0; d < HDd; d++) acc[d] += p * vr[d];
        }
    }

    float inv = 1.f / lsum;
    float* op = o + (size_t)(b * Lseq + l) * Dm + h * HDd;
    #pragma unroll
    for (int d = 0; d < HDd; d++) op[d] = acc[d] * inv;
}

// ---------------------------------------------------------------------------
// Launch sequence (graph-capturable: kernel launches only)
// ---------------------------------------------------------------------------
extern "C" void kernel_launch(void* const* d_in, const int* in_sizes, int n_in,
                              void* d_out, int out_size) {
    const float* spatial   = (const float*)d_in[0];
    const float* density   = (const float*)d_in[1];
    const float* ce        = (const float*)d_in[2];
    const float* spatial_w = (const float*)d_in[3];
    const float* spatial_b = (const float*)d_in[4];
    const float* cond_w    = (const float*)d_in[5];
    const float* cond_b    = (const float*)d_in[6];
    const float* ln1_g     = (const float*)d_in[7];
    const float* ln1_b     = (const float*)d_in[8];
    const float* qkv_w     = (const float*)d_in[9];
    const float* q_scale   = (const float*)d_in[10];
    const float* k_scale   = (const float*)d_in[11];
    const float* proj_w    = (const float*)d_in[12];
    const float* proj_b    = (const float*)d_in[13];
    const float* dscale    = (const float*)d_in[14];
    const float* dbias     = (const float*)d_in[15];
    const float* ln2_g     = (const float*)d_in[16];
    const float* ln2_b     = (const float*)d_in[17];
    const float* mlp_w1    = (const float*)d_in[18];
    const float* mlp_b1    = (const float*)d_in[19];
    const float* mlp_w2    = (const float*)d_in[20];
    const float* mlp_b2    = (const float*)d_in[21];
    const float* out_w     = (const float*)d_in[22];
    const float* out_b     = (const float*)d_in[23];

    float *x, *h, *qkv, *o, *mlp, *cond;
    cudaGetSymbolAddress((void**)&x,    g_x);
    cudaGetSymbolAddress((void**)&h,    g_h);
    cudaGetSymbolAddress((void**)&qkv,  g_qkv);
    cudaGetSymbolAddress((void**)&o,    g_o);
    cudaGetSymbolAddress((void**)&mlp,  g_mlp);
    cudaGetSymbolAddress((void**)&cond, g_cond);

    cond_kernel<<<(Bsz * Dm + 255) / 256, 256>>>(ce, cond_w, cond_b, cond);
    gemm_kernel<true, false, false, true><<<dim3(Dm / GBN, NTOK / GBM), 256>>>(
        spatial, spatial_w, spatial_b, nullptr, cond, x, NTOK, Dm, Dm);

    for (int i = 0; i < NLn; i++) {
        layernorm_kernel<<<NTOK, 256>>>(x, ln1_g + i * Dm, ln1_b + i * Dm, h);

        gemm_kernel<false, false, false, false>
            <<<dim3(3 * Dm / GBN, NTOK / GBM), 256>>>(
            h, qkv_w + (size_t)i * Dm * 3 * Dm, nullptr, nullptr, nullptr,
            qkv, NTOK, 3 * Dm, Dm);

        rmsrope_kernel<<<NTOK, 768>>>(qkv, q_scale + i * HDd, k_scale + i * HDd);

        attn_kernel<<<dim3(Lseq / 128, NHn, Bsz), 128>>>(
            qkv, o, density, dscale, dbias, i);

        gemm_kernel<true, false, true, false>
            <<<dim3(Dm / GBN, NTOK / GBM), 256>>>(
            o, proj_w + (size_t)i * Dm * Dm, proj_b + i * Dm, x, nullptr,
            x, NTOK, Dm, Dm);

        layernorm_kernel<<<NTOK, 256>>>(x, ln2_g + i * Dm, ln2_b + i * Dm, h);

        gemm_kernel<true, true, false, false>
            <<<dim3(MLPd / GBN, NTOK / GBM), 256>>>(
            h, mlp_w1 + (size_t)i * Dm * MLPd, mlp_b1 + i * MLPd, nullptr,
            nullptr, mlp, NTOK, MLPd, Dm);

        gemm_kernel<true, false, true, false>
            <<<dim3(Dm / GBN, NTOK / GBM), 256>>>(
            mlp, mlp_w2 + (size_t)i * MLPd * Dm, mlp_b2 + i * Dm, x, nullptr,
            x, NTOK, Dm, MLPd);
    }

    gemm_kernel<true, false, false, false>
        <<<dim3(Dm / GBN, NTOK / GBM), 256>>>(
        x, out_w, out_b, nullptr, nullptr, (float*)d_out, NTOK, Dm, Dm);
}

// round 7
// speedup vs baseline: 1.6390x; 1.6390x over previous
#include <cuda_runtime.h>
#include <cuda_bf16.h>
#include <math.h>

// Problem constants
#define Bsz  2
#define Lseq 1024
#define Dm   768
#define NHn  12
#define HDd  64
#define NLn  6
#define MLPd 3072
#define NTOK (Bsz * Lseq)   // 2048
#define NBH  (Bsz * NHn)    // 24

// TF32 rounding (round-to-nearest, matches cuBLAS input conversion)
__device__ __forceinline__ float tf32r(float x) {
    asm("cvt.rna.tf32.f32 %0, %0;" : "+f"(x));
    return x;
}

// m16n8k8 tf32 mma, fp32 accumulate
__device__ __forceinline__ void mma_tf32(float* c, const float* a, const float* b) {
    asm volatile(
        "mma.sync.aligned.m16n8k8.row.col.f32.tf32.tf32.f32 "
        "{%0,%1,%2,%3}, {%4,%5,%6,%7}, {%8,%9}, {%0,%1,%2,%3};\n"
        : "+f"(c[0]), "+f"(c[1]), "+f"(c[2]), "+f"(c[3])
        : "r"(__float_as_uint(a[0])), "r"(__float_as_uint(a[1])),
          "r"(__float_as_uint(a[2])), "r"(__float_as_uint(a[3])),
          "r"(__float_as_uint(b[0])), "r"(__float_as_uint(b[1])));
}

// ---------------------------------------------------------------------------
// Scratch (static device globals; no allocation)
// ---------------------------------------------------------------------------
__device__ float g_x     [NTOK * Dm];
__device__ float g_h     [NTOK * Dm];
__device__ float g_qkv   [NTOK * 3 * Dm];
__device__ float g_o     [NTOK * Dm];
__device__ float g_mlp   [NTOK * MLPd];
__device__ float g_cond  [Bsz * Dm];
__device__ float g_scores[(size_t)NBH * Lseq * Lseq];   // 100.7 MB

// ---------------------------------------------------------------------------
// cond_out[b,n] = ce[b,:] @ cond_w[:,n] + cond_b[n]
// ---------------------------------------------------------------------------
__global__ void cond_kernel(const float* __restrict__ ce,
                            const float* __restrict__ w,
                            const float* __restrict__ cb,
                            float* __restrict__ out) {
    int idx = blockIdx.x * blockDim.x + threadIdx.x;
    if (idx >= Bsz * Dm) return;
    int b = idx / Dm, n = idx % Dm;
    float s = 0.f;
    const float* cer = ce + b * 1536;
    #pragma unroll 4
    for (int k = 0; k < 1536; k++) s += cer[k] * w[k * Dm + n];
    out[idx] = s + cb[n];
}

// ---------------------------------------------------------------------------
// TF32 tensor-core GEMM: C[M,N] = A[M,K] @ B[K,N]  (+bias +cond +gelu +res)
// Tiles 128x128x32, 256 threads = 8 warps (4m x 2n), warp tile 32x64.
// ---------------------------------------------------------------------------
#define TBM 128
#define TBN 128
#define TBK 32

template<bool BIAS, bool GELU_F, bool RES, bool COND>
__global__ __launch_bounds__(256)
void mma_gemm(const float* __restrict__ A, const float* __restrict__ Bm,
              const float* __restrict__ bias, const float* __restrict__ res,
              const float* __restrict__ cond, float* __restrict__ C,
              int M, int N, int K) {
    __shared__ float As[TBM][TBK + 4];   // row-major [m][k]
    __shared__ float Bs[TBK][TBN + 4];   // row-major [k][n]

    const int tid  = threadIdx.x;
    const int bm   = blockIdx.y * TBM;
    const int bn   = blockIdx.x * TBN;
    const int warp = tid >> 5, lane = tid & 31;
    const int wm = warp >> 1;            // 0..3
    const int wn = warp & 1;             // 0..1
    const int gid = lane >> 2, tig = lane & 3;
    const int m_base = wm * 32;
    const int n_base = wn * 64;

    const int ar = tid >> 3;             // 0..31 (+i*32)
    const int ac = (tid & 7) * 4;        // 0..28
    const int br = tid >> 3;             // 0..31

    float acc[2][8][4];
    #pragma unroll
    for (int mt = 0; mt < 2; mt++)
        #pragma unroll
        for (int nt = 0; nt < 8; nt++)
            #pragma unroll
            for (int i = 0; i < 4; i++) acc[mt][nt][i] = 0.f;

    for (int k0 = 0; k0 < K; k0 += TBK) {
        #pragma unroll
        for (int i = 0; i < 4; i++) {
            int r = ar + i * 32;
            float4 v = *(const float4*)&A[(size_t)(bm + r) * K + k0 + ac];
            v.x = tf32r(v.x); v.y = tf32r(v.y); v.z = tf32r(v.z); v.w = tf32r(v.w);
            *(float4*)&As[r][ac] = v;
        }
        #pragma unroll
        for (int i = 0; i < 4; i++) {
            int c = (tid & 7) * 16 + i * 4;
            float4 v = *(const float4*)&Bm[(size_t)(k0 + br) * N + bn + c];
            v.x = tf32r(v.x); v.y = tf32r(v.y); v.z = tf32r(v.z); v.w = tf32r(v.w);
            *(float4*)&Bs[br][c] = v;
        }
        __syncthreads();

        #pragma unroll
        for (int ks = 0; ks < 4; ks++) {
            const int kk = ks * 8;
            float af[2][4], bf[8][2];
            #pragma unroll
            for (int mt = 0; mt < 2; mt++) {
                int r0 = m_base + mt * 16 + gid;
                af[mt][0] = As[r0][kk + tig];
                af[mt][1] = As[r0 + 8][kk + tig];
                af[mt][2] = As[r0][kk + tig + 4];
                af[mt][3] = As[r0 + 8][kk + tig + 4];
            }
            #pragma unroll
            for (int nt = 0; nt < 8; nt++) {
                int c0 = n_base + nt * 8 + gid;
                bf[nt][0] = Bs[kk + tig][c0];
                bf[nt][1] = Bs[kk + tig + 4][c0];
            }
            #pragma unroll
            for (int mt = 0; mt < 2; mt++)
                #pragma unroll
                for (int nt = 0; nt < 8; nt++)
                    mma_tf32(acc[mt][nt], af[mt], bf[nt]);
        }
        __syncthreads();
    }

    // Epilogue: c0,c1 -> row gid; c2,c3 -> row gid+8; cols 2*tig, 2*tig+1
    #pragma unroll
    for (int mt = 0; mt < 2; mt++) {
        #pragma unroll
        for (int nt = 0; nt < 8; nt++) {
            int col = bn + n_base + nt * 8 + tig * 2;
            #pragma unroll
            for (int half = 0; half < 2; half++) {
                int row = bm + m_base + mt * 16 + gid + half * 8;
                float vx = acc[mt][nt][half * 2 + 0];
                float vy = acc[mt][nt][half * 2 + 1];
                if (BIAS) { vx += bias[col]; vy += bias[col + 1]; }
                if (COND) {
                    const float* cp = cond + (row >> 10) * N + col;
                    vx += cp[0]; vy += cp[1];
                }
                if (GELU_F) {
                    vx = 0.5f * vx * (1.f + erff(vx * 0.70710678118654752f));
                    vy = 0.5f * vy * (1.f + erff(vy * 0.70710678118654752f));
                }
                if (RES) {
                    float2 rr = *(const float2*)&res[(size_t)row * N + col];
                    vx += rr.x; vy += rr.y;
                }
                float2 out = make_float2(vx, vy);
                *(float2*)&C[(size_t)row * N + col] = out;
            }
        }
    }
}

// ---------------------------------------------------------------------------
// LayerNorm: one block per token row (768 cols), 256 threads x 3 elems
// ---------------------------------------------------------------------------
__global__ __launch_bounds__(256)
void layernorm_kernel(const float* __restrict__ x, const float* __restrict__ g,
                      const float* __restrict__ b, float* __restrict__ out) {
    int row = blockIdx.x;
    int t = threadIdx.x;
    const float* xr = x + (size_t)row * Dm;
    float v0 = xr[t], v1 = xr[t + 256], v2 = xr[t + 512];
    float s = v0 + v1 + v2;
    float q = v0 * v0 + v1 * v1 + v2 * v2;
    #pragma unroll
    for (int o = 16; o > 0; o >>= 1) {
        s += __shfl_xor_sync(0xffffffffu, s, o);
        q += __shfl_xor_sync(0xffffffffu, q, o);
    }
    __shared__ float ss[8], sq[8];
    int wid = t >> 5, lane = t & 31;
    if (!lane) { ss[wid] = s; sq[wid] = q; }
    __syncthreads();
    if (t == 0) {
        float S = 0.f, Q = 0.f;
        #pragma unroll
        for (int i = 0; i < 8; i++) { S += ss[i]; Q += sq[i]; }
        float m = S * (1.f / Dm);
        float var = Q * (1.f / Dm) - m * m;
        ss[0] = m;
        sq[0] = rsqrtf(var + 1e-5f);
    }
    __syncthreads();
    float m = ss[0], r = sq[0];
    float* orow = out + (size_t)row * Dm;
    orow[t]       = (v0 - m) * r * g[t]       + b[t];
    orow[t + 256] = (v1 - m) * r * g[t + 256] + b[t + 256];
    orow[t + 512] = (v2 - m) * r * g[t + 512] + b[t + 512];
}

// ---------------------------------------------------------------------------
// Fused RMSNorm + RoPE on q,k (in place), fp64 transcendentals (proven pass).
// ---------------------------------------------------------------------------
__global__ __launch_bounds__(768)
void rmsrope_kernel(float* __restrict__ qkv,
                    const float* __restrict__ qs,
                    const float* __restrict__ ks) {
    int token = blockIdx.x;
    int w = threadIdx.x >> 5;
    int lane = threadIdx.x & 31;
    int isK = (w >= NHn);
    int h = isK ? w - NHn : w;
    float* base = qkv + (size_t)token * (3 * Dm) + (isK ? Dm : 0) + h * HDd;
    const float* sc = isK ? ks : qs;

    float x0 = base[2 * lane], x1 = base[2 * lane + 1];
    float s = x0 * x0 + x1 * x1;
    #pragma unroll
    for (int o = 16; o > 0; o >>= 1) s += __shfl_xor_sync(0xffffffffu, s, o);
    float r = rsqrtf(s * (1.f / HDd) + 1e-6f);
    float y0 = x0 * r * sc[2 * lane];
    float y1 = x1 * r * sc[2 * lane + 1];

    int l = token & (Lseq - 1);
    int col = l & 31, rowp = l >> 5;
    double pos, fidx;
    if (lane < 16) { pos = (double)col;  fidx = (double)lane; }
    else           { pos = (double)rowp; fidx = (double)(lane - 16); }
    double omega = exp(fidx * -0.5756462732485115);
    double ang = pos * omega;
    float c  = (float)cos(ang);
    float sn = (float)sin(ang);
    base[2 * lane]     = c * y0 - sn * y1;
    base[2 * lane + 1] = sn * y0 + c * y1;
}

// ---------------------------------------------------------------------------
// Scores: S[z,l,m] = (q[z,l,:].k[z,m,:]) * 0.125 + (dscale*dens[b,l]+dbias)
// Exact fp32, d-order ascending (matches passing kernel). 128x128 tile,
// 256 threads, 8x8 per thread, d in 4 slabs of 16.
// ---------------------------------------------------------------------------
__global__ __launch_bounds__(256)
void scores_kernel(const float* __restrict__ qkv, const float* __restrict__ dens,
                   const float* __restrict__ dscale, const float* __restrict__ dbias,
                   int layer, float* __restrict__ S) {
    __shared__ float Qs[16][132];
    __shared__ float Ks[16][132];
    const int tid  = threadIdx.x;
    const int mkey = blockIdx.x * 128;
    const int mq   = blockIdx.y * 128;
    const int z    = blockIdx.z;           // b*NH + h
    const int b = z / NHn, h = z % NHn;
    const int tr = (tid / 16) * 8, tc = (tid % 16) * 8;
    const int lr = tid >> 1;

    float acc[8][8];
    #pragma unroll
    for (int i = 0; i < 8; i++)
        #pragma unroll
        for (int j = 0; j < 8; j++) acc[i][j] = 0.f;

    for (int d0 = 0; d0 < HDd; d0 += 16) {
        #pragma unroll
        for (int i = 0; i < 2; i++) {
            int c = (tid & 1) * 8 + i * 4;
            const float* qp = qkv + (size_t)(b * Lseq + mq + lr) * (3 * Dm)
                                  + h * HDd + d0 + c;
            float4 v = *(const float4*)qp;
            Qs[c + 0][lr] = v.x; Qs[c + 1][lr] = v.y;
            Qs[c + 2][lr] = v.z; Qs[c + 3][lr] = v.w;
            const float* kp = qkv + (size_t)(b * Lseq + mkey + lr) * (3 * Dm)
                                  + Dm + h * HDd + d0 + c;
            float4 u = *(const float4*)kp;
            Ks[c + 0][lr] = u.x; Ks[c + 1][lr] = u.y;
            Ks[c + 2][lr] = u.z; Ks[c + 3][lr] = u.w;
        }
        __syncthreads();
        #pragma unroll
        for (int kk = 0; kk < 16; kk++) {
            float ra[8], rb[8];
            #pragma unroll
            for (int i = 0; i < 8; i++) ra[i] = Qs[kk][tr + i];
            #pragma unroll
            for (int j = 0; j < 8; j++) rb[j] = Ks[kk][tc + j];
            #pragma unroll
            for (int i = 0; i < 8; i++)
                #pragma unroll
                for (int j = 0; j < 8; j++) acc[i][j] += ra[i] * rb[j];
        }
        __syncthreads();
    }

    const float dsc = dscale[layer], dbi = dbias[layer];
    #pragma unroll
    for (int i = 0; i < 8; i++) {
        int l = mq + tr + i;
        float bv = dsc * dens[b * Lseq + l] + dbi;
        float* Sp = S + ((size_t)z * Lseq + l) * Lseq + mkey + tc;
        #pragma unroll
        for (int j = 0; j < 8; j++) Sp[j] = acc[i][j] * 0.125f + bv;
    }
}

// ---------------------------------------------------------------------------
// Exact row softmax over 1024 keys, in place. max is associative (exact);
// sum reassociation ~1e-7. p/sum division like the reference.
// ---------------------------------------------------------------------------
__global__ __launch_bounds__(256)
void softmax_kernel(float* __restrict__ S) {
    const int t = threadIdx.x;
    float* p = S + (size_t)blockIdx.x * Lseq;
    float v[4];
    #pragma unroll
    for (int i = 0; i < 4; i++) v[i] = p[t + i * 256];

    float m = fmaxf(fmaxf(v[0], v[1]), fmaxf(v[2], v[3]));
    #pragma unroll
    for (int o = 16; o > 0; o >>= 1) m = fmaxf(m, __shfl_xor_sync(0xffffffffu, m, o));
    __shared__ float sm[8];
    int wid = t >> 5, lane = t & 31;
    if (!lane) sm[wid] = m;
    __syncthreads();
    if (t == 0) {
        float M = sm[0];
        #pragma unroll
        for (int i = 1; i < 8; i++) M = fmaxf(M, sm[i]);
        sm[0] = M;
    }
    __syncthreads();
    m = sm[0];

    float e[4], s = 0.f;
    #pragma unroll
    for (int i = 0; i < 4; i++) { e[i] = expf(v[i] - m); s += e[i]; }
    #pragma unroll
    for (int o = 16; o > 0; o >>= 1) s += __shfl_xor_sync(0xffffffffu, s, o);
    __shared__ float sq[8];
    if (!lane) sq[wid] = s;
    __syncthreads();
    if (t == 0) {
        float Ssum = 0.f;
        #pragma unroll
        for (int i = 0; i < 8; i++) Ssum += sq[i];
        sq[0] = Ssum;
    }
    __syncthreads();
    s = sq[0];
    #pragma unroll
    for (int i = 0; i < 4; i++) p[t + i * 256] = e[i] / s;
}

// ---------------------------------------------------------------------------
// PV: O[z,l,d] = sum_m P[z,l,m] * V[z,m,d], exact fp32, m ascending.
// Tile 128(l) x 64(d) x 16(m); 256 threads, 8x4 per thread; 64 k-iters.
// Writes g_o in [token][h*64+d] layout.
// ---------------------------------------------------------------------------
__global__ __launch_bounds__(256)
void pv_kernel(const float* __restrict__ S, const float* __restrict__ qkv,
               float* __restrict__ o) {
    __shared__ float Ps[16][132];
    __shared__ float Vs[16][68];
    const int tid = threadIdx.x;
    const int ml  = blockIdx.x * 128;
    const int z   = blockIdx.y;
    const int b = z / NHn, h = z % NHn;
    const int tr = (tid / 16) * 8, tc = (tid % 16) * 4;
    const int lr = tid >> 1;
    const int vr = tid >> 4, vc = (tid & 15) * 4;

    float acc[8][4];
    #pragma unroll
    for (int i = 0; i < 8; i++)
        #pragma unroll
        for (int j = 0; j < 4; j++) acc[i][j] = 0.f;

    for (int k0 = 0; k0 < Lseq; k0 += 16) {
        #pragma unroll
        for (int i = 0; i < 2; i++) {
            int c = (tid & 1) * 8 + i * 4;
            float4 v = *(const float4*)(S + ((size_t)z * Lseq + ml + lr) * Lseq + k0 + c);
            Ps[c + 0][lr] = v.x; Ps[c + 1][lr] = v.y;
            Ps[c + 2][lr] = v.z; Ps[c + 3][lr] = v.w;
        }
        {
            const float* vp = qkv + (size_t)(b * Lseq + k0 + vr) * (3 * Dm)
                                  + 2 * Dm + h * HDd + vc;
            *(float4*)&Vs[vr][vc] = *(const float4*)vp;
        }
        __syncthreads();
        #pragma unroll
        for (int kk = 0; kk < 16; kk++) {
            float ra[8], rb[4];
            #pragma unroll
            for (int i = 0; i < 8; i++) ra[i] = Ps[kk][tr + i];
            #pragma unroll
            for (int j = 0; j < 4; j++) rb[j] = Vs[kk][tc + j];
            #pragma unroll
            for (int i = 0; i < 8; i++)
                #pragma unroll
                for (int j = 0; j < 4; j++) acc[i][j] += ra[i] * rb[j];
        }
        __syncthreads();
    }

    #pragma unroll
    for (int i = 0; i < 8; i++) {
        float* op = o + (size_t)(b * Lseq + ml + tr + i) * Dm + h * HDd + tc;
        #pragma unroll
        for (int j = 0; j < 4; j++) op[j] = acc[i][j];
    }
}

// ---------------------------------------------------------------------------
// Launch sequence (graph-capturable: kernel launches only)
// ---------------------------------------------------------------------------
extern "C" void kernel_launch(void* const* d_in, const int* in_sizes, int n_in,
                              void* d_out, int out_size) {
    const float* spatial   = (const float*)d_in[0];
    const float* density   = (const float*)d_in[1];
    const float* ce        = (const float*)d_in[2];
    const float* spatial_w = (const float*)d_in[3];
    const float* spatial_b = (const float*)d_in[4];
    const float* cond_w    = (const float*)d_in[5];
    const float* cond_b    = (const float*)d_in[6];
    const float* ln1_g     = (const float*)d_in[7];
    const float* ln1_b     = (const float*)d_in[8];
    const float* qkv_w     = (const float*)d_in[9];
    const float* q_scale   = (const float*)d_in[10];
    const float* k_scale   = (const float*)d_in[11];
    const float* proj_w    = (const float*)d_in[12];
    const float* proj_b    = (const float*)d_in[13];
    const float* dscale    = (const float*)d_in[14];
    const float* dbias     = (const float*)d_in[15];
    const float* ln2_g     = (const float*)d_in[16];
    const float* ln2_b     = (const float*)d_in[17];
    const float* mlp_w1    = (const float*)d_in[18];
    const float* mlp_b1    = (const float*)d_in[19];
    const float* mlp_w2    = (const float*)d_in[20];
    const float* mlp_b2    = (const float*)d_in[21];
    const float* out_w     = (const float*)d_in[22];
    const float* out_b     = (const float*)d_in[23];

    float *x, *h, *qkv, *o, *mlp, *cond, *scores;
    cudaGetSymbolAddress((void**)&x,      g_x);
    cudaGetSymbolAddress((void**)&h,      g_h);
    cudaGetSymbolAddress((void**)&qkv,    g_qkv);
    cudaGetSymbolAddress((void**)&o,      g_o);
    cudaGetSymbolAddress((void**)&mlp,    g_mlp);
    cudaGetSymbolAddress((void**)&cond,   g_cond);
    cudaGetSymbolAddress((void**)&scores, g_scores);

    cond_kernel<<<(Bsz * Dm + 255) / 256, 256>>>(ce, cond_w, cond_b, cond);
    mma_gemm<true, false, false, true><<<dim3(Dm / TBN, NTOK / TBM), 256>>>(
        spatial, spatial_w, spatial_b, nullptr, cond, x, NTOK, Dm, Dm);

    for (int i = 0; i < NLn; i++) {
        layernorm_kernel<<<NTOK, 256>>>(x, ln1_g + i * Dm, ln1_b + i * Dm, h);

        mma_gemm<false, false, false, false>
            <<<dim3(3 * Dm / TBN, NTOK / TBM), 256>>>(
            h, qkv_w + (size_t)i * Dm * 3 * Dm, nullptr, nullptr, nullptr,
            qkv, NTOK, 3 * Dm, Dm);

        rmsrope_kernel<<<NTOK, 768>>>(qkv, q_scale + i * HDd, k_scale + i * HDd);

        scores_kernel<<<dim3(Lseq / 128, Lseq / 128, NBH), 256>>>(
            qkv, density, dscale, dbias, i, scores);
        softmax_kernel<<<NBH * Lseq, 256>>>(scores);
        pv_kernel<<<dim3(Lseq / 128, NBH), 256>>>(scores, qkv, o);

        mma_gemm<true, false, true, false>
            <<<dim3(Dm / TBN, NTOK / TBM), 256>>>(
            o, proj_w + (size_t)i * Dm * Dm, proj_b + i * Dm, x, nullptr,
            x, NTOK, Dm, Dm);

        layernorm_kernel<<<NTOK, 256>>>(x, ln2_g + i * Dm, ln2_b + i * Dm, h);

        mma_gemm<true, true, false, false>
            <<<dim3(MLPd / TBN, NTOK / TBM), 256>>>(
            h, mlp_w1 + (size_t)i * Dm * MLPd, mlp_b1 + i * MLPd, nullptr,
            nullptr, mlp, NTOK, MLPd, Dm);

        mma_gemm<true, false, true, false>
            <<<dim3(Dm / TBN, NTOK / TBM), 256>>>(
            mlp, mlp_w2 + (size_t)i * MLPd * Dm, mlp_b2 + i * Dm, x, nullptr,
            x, NTOK, Dm, MLPd);
    }

    mma_gemm<true, false, false, false>
        <<<dim3(Dm / TBN, NTOK / TBM), 256>>>(
        x, out_w, out_b, nullptr, nullptr, (float*)d_out, NTOK, Dm, Dm);
}

// round 8
// speedup vs baseline: 2.0679x; 1.2617x over previous
#include <cuda_runtime.h>
#include <cuda_bf16.h>
#include <math.h>

// Problem constants
#define Bsz  2
#define Lseq 1024
#define Dm   768
#define NHn  12
#define HDd  64
#define NLn  6
#define MLPd 3072
#define NTOK (Bsz * Lseq)   // 2048
#define NBH  (Bsz * NHn)    // 24

// TF32 rounding (round-to-nearest, matches cuBLAS input conversion)
__device__ __forceinline__ float tf32r(float x) {
    asm("cvt.rna.tf32.f32 %0, %0;" : "+f"(x));
    return x;
}
__device__ __forceinline__ float4 tf32r4(float4 v) {
    v.x = tf32r(v.x); v.y = tf32r(v.y); v.z = tf32r(v.z); v.w = tf32r(v.w);
    return v;
}

// m16n8k8 tf32 mma, fp32 accumulate
__device__ __forceinline__ void mma_tf32(float* c, const float* a, const float* b) {
    asm volatile(
        "mma.sync.aligned.m16n8k8.row.col.f32.tf32.tf32.f32 "
        "{%0,%1,%2,%3}, {%4,%5,%6,%7}, {%8,%9}, {%0,%1,%2,%3};\n"
        : "+f"(c[0]), "+f"(c[1]), "+f"(c[2]), "+f"(c[3])
        : "r"(__float_as_uint(a[0])), "r"(__float_as_uint(a[1])),
          "r"(__float_as_uint(a[2])), "r"(__float_as_uint(a[3])),
          "r"(__float_as_uint(b[0])), "r"(__float_as_uint(b[1])));
}

// ---------------------------------------------------------------------------
// Scratch (static device globals; no allocation)
// ---------------------------------------------------------------------------
__device__ float g_x     [NTOK * Dm];
__device__ float g_h     [NTOK * Dm];
__device__ float g_qkv   [NTOK * 3 * Dm];
__device__ float g_o     [NTOK * Dm];
__device__ float g_mlp   [NTOK * MLPd];
__device__ float g_cond  [Bsz * Dm];
__device__ float g_scores[(size_t)NBH * Lseq * Lseq];   // 100.7 MB

// ---------------------------------------------------------------------------
// cond_out[b,n] = ce[b,:] @ cond_w[:,n] + cond_b[n]
// ---------------------------------------------------------------------------
__global__ void cond_kernel(const float* __restrict__ ce,
                            const float* __restrict__ w,
                            const float* __restrict__ cb,
                            float* __restrict__ out) {
    int idx = blockIdx.x * blockDim.x + threadIdx.x;
    if (idx >= Bsz * Dm) return;
    int b = idx / Dm, n = idx % Dm;
    float s = 0.f;
    const float* cer = ce + b * 1536;
    #pragma unroll 4
    for (int k = 0; k < 1536; k++) s += cer[k] * w[k * Dm + n];
    out[idx] = s + cb[n];
}

// ---------------------------------------------------------------------------
// TF32 tensor-core GEMM with register prefetch:
// C[M,N] = A[M,K] @ B[K,N]  (+bias +cond +gelu +res)
// Tiles 128x128x32, 256 threads = 8 warps (4m x 2n), warp tile 32x64.
// ---------------------------------------------------------------------------
#define TBM 128
#define TBN 128
#define TBK 32

template<bool BIAS, bool GELU_F, bool RES, bool COND>
__global__ __launch_bounds__(256)
void mma_gemm(const float* __restrict__ A, const float* __restrict__ Bm,
              const float* __restrict__ bias, const float* __restrict__ res,
              const float* __restrict__ cond, float* __restrict__ C,
              int M, int N, int K) {
    __shared__ float As[TBM][TBK + 4];   // [m][k]
    __shared__ float Bs[TBK][TBN + 4];   // [k][n]

    const int tid  = threadIdx.x;
    const int bm   = blockIdx.y * TBM;
    const int bn   = blockIdx.x * TBN;
    const int warp = tid >> 5, lane = tid & 31;
    const int wm = warp >> 1;            // 0..3
    const int wn = warp & 1;             // 0..1
    const int gid = lane >> 2, tig = lane & 3;
    const int m_base = wm * 32;
    const int n_base = wn * 64;

    const int ar = tid >> 3;             // 0..31 (+i*32)
    const int ac = (tid & 7) * 4;        // 0..28
    const int br = tid >> 3;             // 0..31
    const int bc = (tid & 7) * 16;       // +i*4

    float acc[2][8][4];
    #pragma unroll
    for (int mt = 0; mt < 2; mt++)
        #pragma unroll
        for (int nt = 0; nt < 8; nt++)
            #pragma unroll
            for (int i = 0; i < 4; i++) acc[mt][nt][i] = 0.f;

    float4 pa[4], pb[4];
    #pragma unroll
    for (int i = 0; i < 4; i++) {
        pa[i] = *(const float4*)&A[(size_t)(bm + ar + i * 32) * K + ac];
        pb[i] = *(const float4*)&Bm[(size_t)br * N + bn + bc + i * 4];
    }

    for (int k0 = 0; k0 < K; k0 += TBK) {
        #pragma unroll
        for (int i = 0; i < 4; i++) {
            *(float4*)&As[ar + i * 32][ac] = tf32r4(pa[i]);
            *(float4*)&Bs[br][bc + i * 4]  = tf32r4(pb[i]);
        }
        __syncthreads();
        if (k0 + TBK < K) {
            #pragma unroll
            for (int i = 0; i < 4; i++) {
                pa[i] = *(const float4*)&A[(size_t)(bm + ar + i * 32) * K + k0 + TBK + ac];
                pb[i] = *(const float4*)&Bm[(size_t)(k0 + TBK + br) * N + bn + bc + i * 4];
            }
        }

        #pragma unroll
        for (int ks = 0; ks < 4; ks++) {
            const int kk = ks * 8;
            float af[2][4], bf[8][2];
            #pragma unroll
            for (int mt = 0; mt < 2; mt++) {
                int r0 = m_base + mt * 16 + gid;
                af[mt][0] = As[r0][kk + tig];
                af[mt][1] = As[r0 + 8][kk + tig];
                af[mt][2] = As[r0][kk + tig + 4];
                af[mt][3] = As[r0 + 8][kk + tig + 4];
            }
            #pragma unroll
            for (int nt = 0; nt < 8; nt++) {
                int c0 = n_base + nt * 8 + gid;
                bf[nt][0] = Bs[kk + tig][c0];
                bf[nt][1] = Bs[kk + tig + 4][c0];
            }
            #pragma unroll
            for (int mt = 0; mt < 2; mt++)
                #pragma unroll
                for (int nt = 0; nt < 8; nt++)
                    mma_tf32(acc[mt][nt], af[mt], bf[nt]);
        }
        __syncthreads();
    }

    #pragma unroll
    for (int mt = 0; mt < 2; mt++) {
        #pragma unroll
        for (int nt = 0; nt < 8; nt++) {
            int col = bn + n_base + nt * 8 + tig * 2;
            #pragma unroll
            for (int half = 0; half < 2; half++) {
                int row = bm + m_base + mt * 16 + gid + half * 8;
                float vx = acc[mt][nt][half * 2 + 0];
                float vy = acc[mt][nt][half * 2 + 1];
                if (BIAS) { vx += bias[col]; vy += bias[col + 1]; }
                if (COND) {
                    const float* cp = cond + (row >> 10) * N + col;
                    vx += cp[0]; vy += cp[1];
                }
                if (GELU_F) {
                    vx = 0.5f * vx * (1.f + erff(vx * 0.70710678118654752f));
                    vy = 0.5f * vy * (1.f + erff(vy * 0.70710678118654752f));
                }
                if (RES) {
                    float2 rr = *(const float2*)&res[(size_t)row * N + col];
                    vx += rr.x; vy += rr.y;
                }
                float2 out = make_float2(vx, vy);
                *(float2*)&C[(size_t)row * N + col] = out;
            }
        }
    }
}

// ---------------------------------------------------------------------------
// LayerNorm: one block per token row (768 cols), 256 threads x 3 elems
// ---------------------------------------------------------------------------
__global__ __launch_bounds__(256)
void layernorm_kernel(const float* __restrict__ x, const float* __restrict__ g,
                      const float* __restrict__ b, float* __restrict__ out) {
    int row = blockIdx.x;
    int t = threadIdx.x;
    const float* xr = x + (size_t)row * Dm;
    float v0 = xr[t], v1 = xr[t + 256], v2 = xr[t + 512];
    float s = v0 + v1 + v2;
    float q = v0 * v0 + v1 * v1 + v2 * v2;
    #pragma unroll
    for (int o = 16; o > 0; o >>= 1) {
        s += __shfl_xor_sync(0xffffffffu, s, o);
        q += __shfl_xor_sync(0xffffffffu, q, o);
    }
    __shared__ float ss[8], sq[8];
    int wid = t >> 5, lane = t & 31;
    if (!lane) { ss[wid] = s; sq[wid] = q; }
    __syncthreads();
    if (t == 0) {
        float S = 0.f, Q = 0.f;
        #pragma unroll
        for (int i = 0; i < 8; i++) { S += ss[i]; Q += sq[i]; }
        float m = S * (1.f / Dm);
        float var = Q * (1.f / Dm) - m * m;
        ss[0] = m;
        sq[0] = rsqrtf(var + 1e-5f);
    }
    __syncthreads();
    float m = ss[0], r = sq[0];
    float* orow = out + (size_t)row * Dm;
    orow[t]       = (v0 - m) * r * g[t]       + b[t];
    orow[t + 256] = (v1 - m) * r * g[t + 256] + b[t + 256];
    orow[t + 512] = (v2 - m) * r * g[t + 512] + b[t + 512];
}

// ---------------------------------------------------------------------------
// Fused RMSNorm + RoPE on q,k (in place), fp64 transcendentals (proven pass).
// ---------------------------------------------------------------------------
__global__ __launch_bounds__(768)
void rmsrope_kernel(float* __restrict__ qkv,
                    const float* __restrict__ qs,
                    const float* __restrict__ ks) {
    int token = blockIdx.x;
    int w = threadIdx.x >> 5;
    int lane = threadIdx.x & 31;
    int isK = (w >= NHn);
    int h = isK ? w - NHn : w;
    float* base = qkv + (size_t)token * (3 * Dm) + (isK ? Dm : 0) + h * HDd;
    const float* sc = isK ? ks : qs;

    float x0 = base[2 * lane], x1 = base[2 * lane + 1];
    float s = x0 * x0 + x1 * x1;
    #pragma unroll
    for (int o = 16; o > 0; o >>= 1) s += __shfl_xor_sync(0xffffffffu, s, o);
    float r = rsqrtf(s * (1.f / HDd) + 1e-6f);
    float y0 = x0 * r * sc[2 * lane];
    float y1 = x1 * r * sc[2 * lane + 1];

    int l = token & (Lseq - 1);
    int col = l & 31, rowp = l >> 5;
    double pos, fidx;
    if (lane < 16) { pos = (double)col;  fidx = (double)lane; }
    else           { pos = (double)rowp; fidx = (double)(lane - 16); }
    double omega = exp(fidx * -0.5756462732485115);
    double ang = pos * omega;
    float c  = (float)cos(ang);
    float sn = (float)sin(ang);
    base[2 * lane]     = c * y0 - sn * y1;
    base[2 * lane + 1] = sn * y0 + c * y1;
}

// ---------------------------------------------------------------------------
// Scores via tf32 mma: S[z,l,m] = (q.k)*0.125 + (dscale*dens+dbias)
// M=128 q-rows, N=128 keys, K=64 d (2 chunks). K matrix [key][d] is natural
// col-major B; loader transposes into Bs[d][key] (conflict-free stores).
// ---------------------------------------------------------------------------
__global__ __launch_bounds__(256)
void scores_mma(const float* __restrict__ qkv, const float* __restrict__ dens,
                const float* __restrict__ dscale, const float* __restrict__ dbias,
                int layer, float* __restrict__ S) {
    __shared__ float As[128][36];
    __shared__ float Bs[32][132];

    const int tid  = threadIdx.x;
    const int mkey = blockIdx.x * 128;
    const int mq   = blockIdx.y * 128;
    const int z    = blockIdx.z;
    const int b = z / NHn, h = z % NHn;
    const int warp = tid >> 5, lane = tid & 31;
    const int wm = warp >> 1, wn = warp & 1;
    const int gid = lane >> 2, tig = lane & 3;
    const int m_base = wm * 32, n_base = wn * 64;

    const float* Qb = qkv + (size_t)(b * Lseq + mq) * (3 * Dm) + h * HDd;
    const float* Kb = qkv + (size_t)(b * Lseq + mkey) * (3 * Dm) + Dm + h * HDd;

    const int ar = tid >> 3, ac = (tid & 7) * 4;
    const int key = tid >> 1, d4b = (tid & 1) * 4;   // d4 = d4b + i*8

    float acc[2][8][4];
    #pragma unroll
    for (int mt = 0; mt < 2; mt++)
        #pragma unroll
        for (int nt = 0; nt < 8; nt++)
            #pragma unroll
            for (int i = 0; i < 4; i++) acc[mt][nt][i] = 0.f;

    float4 pa[4], pb[4];
    #pragma unroll
    for (int i = 0; i < 4; i++) {
        pa[i] = *(const float4*)&Qb[(size_t)(ar + i * 32) * (3 * Dm) + ac];
        pb[i] = *(const float4*)&Kb[(size_t)key * (3 * Dm) + d4b + i * 8];
    }

    for (int k0 = 0; k0 < HDd; k0 += 32) {
        #pragma unroll
        for (int i = 0; i < 4; i++) {
            *(float4*)&As[ar + i * 32][ac] = tf32r4(pa[i]);
            int d4 = d4b + i * 8;
            Bs[d4 + 0][key] = tf32r(pb[i].x);
            Bs[d4 + 1][key] = tf32r(pb[i].y);
            Bs[d4 + 2][key] = tf32r(pb[i].z);
            Bs[d4 + 3][key] = tf32r(pb[i].w);
        }
        __syncthreads();
        if (k0 + 32 < HDd) {
            #pragma unroll
            for (int i = 0; i < 4; i++) {
                pa[i] = *(const float4*)&Qb[(size_t)(ar + i * 32) * (3 * Dm) + k0 + 32 + ac];
                pb[i] = *(const float4*)&Kb[(size_t)key * (3 * Dm) + k0 + 32 + d4b + i * 8];
            }
        }

        #pragma unroll
        for (int ks = 0; ks < 4; ks++) {
            const int kk = ks * 8;
            float af[2][4], bf[8][2];
            #pragma unroll
            for (int mt = 0; mt < 2; mt++) {
                int r0 = m_base + mt * 16 + gid;
                af[mt][0] = As[r0][kk + tig];
                af[mt][1] = As[r0 + 8][kk + tig];
                af[mt][2] = As[r0][kk + tig + 4];
                af[mt][3] = As[r0 + 8][kk + tig + 4];
            }
            #pragma unroll
            for (int nt = 0; nt < 8; nt++) {
                int c0 = n_base + nt * 8 + gid;
                bf[nt][0] = Bs[kk + tig][c0];
                bf[nt][1] = Bs[kk + tig + 4][c0];
            }
            #pragma unroll
            for (int mt = 0; mt < 2; mt++)
                #pragma unroll
                for (int nt = 0; nt < 8; nt++)
                    mma_tf32(acc[mt][nt], af[mt], bf[nt]);
        }
        __syncthreads();
    }

    const float dsc = dscale[layer], dbi = dbias[layer];
    #pragma unroll
    for (int mt = 0; mt < 2; mt++) {
        #pragma unroll
        for (int nt = 0; nt < 8; nt++) {
            int col = mkey + n_base + nt * 8 + tig * 2;
            #pragma unroll
            for (int half = 0; half < 2; half++) {
                int row = mq + m_base + mt * 16 + gid + half * 8;
                float bv = dsc * dens[b * Lseq + row] + dbi;
                float2 out = make_float2(
                    acc[mt][nt][half * 2 + 0] * 0.125f + bv,
                    acc[mt][nt][half * 2 + 1] * 0.125f + bv);
                *(float2*)&S[((size_t)z * Lseq + row) * Lseq + col] = out;
            }
        }
    }
}

// ---------------------------------------------------------------------------
// Exact row softmax over 1024 keys, in place (proven).
// ---------------------------------------------------------------------------
__global__ __launch_bounds__(256)
void softmax_kernel(float* __restrict__ S) {
    const int t = threadIdx.x;
    float* p = S + (size_t)blockIdx.x * Lseq;
    float v[4];
    #pragma unroll
    for (int i = 0; i < 4; i++) v[i] = p[t + i * 256];

    float m = fmaxf(fmaxf(v[0], v[1]), fmaxf(v[2], v[3]));
    #pragma unroll
    for (int o = 16; o > 0; o >>= 1) m = fmaxf(m, __shfl_xor_sync(0xffffffffu, m, o));
    __shared__ float sm[8];
    int wid = t >> 5, lane = t & 31;
    if (!lane) sm[wid] = m;
    __syncthreads();
    if (t == 0) {
        float M = sm[0];
        #pragma unroll
        for (int i = 1; i < 8; i++) M = fmaxf(M, sm[i]);
        sm[0] = M;
    }
    __syncthreads();
    m = sm[0];

    float e[4], s = 0.f;
    #pragma unroll
    for (int i = 0; i < 4; i++) { e[i] = expf(v[i] - m); s += e[i]; }
    #pragma unroll
    for (int o = 16; o > 0; o >>= 1) s += __shfl_xor_sync(0xffffffffu, s, o);
    __shared__ float sq[8];
    if (!lane) sq[wid] = s;
    __syncthreads();
    if (t == 0) {
        float Ssum = 0.f;
        #pragma unroll
        for (int i = 0; i < 8; i++) Ssum += sq[i];
        sq[0] = Ssum;
    }
    __syncthreads();
    s = sq[0];
    #pragma unroll
    for (int i = 0; i < 4; i++) p[t + i * 256] = e[i] / s;
}

// ---------------------------------------------------------------------------
// PV via tf32 mma: O[z,l,d] = sum_m P[z,l,m] V[z,m,d].
// M=128 l, N=64 d, K=1024 m (32-chunks). V [m][d] is the natural dense-B.
// 8 warps: 4m x 2n, warp tile 32x32 (nt=4). Writes o[token][h*64+d].
// ---------------------------------------------------------------------------
__global__ __launch_bounds__(256)
void pv_mma(const float* __restrict__ S, const float* __restrict__ qkv,
            float* __restrict__ o) {
    __shared__ float As[128][36];
    __shared__ float Bs[32][68];

    const int tid = threadIdx.x;
    const int ml  = blockIdx.x * 128;
    const int z   = blockIdx.y;
    const int b = z / NHn, h = z % NHn;
    const int warp = tid >> 5, lane = tid & 31;
    const int wm = warp >> 1, wn = warp & 1;
    const int gid = lane >> 2, tig = lane & 3;
    const int m_base = wm * 32, n_base = wn * 32;

    const float* Pb = S + ((size_t)z * Lseq + ml) * Lseq;
    const float* Vb = qkv + (size_t)(b * Lseq) * (3 * Dm) + 2 * Dm + h * HDd;

    const int ar = tid >> 3, ac = (tid & 7) * 4;
    const int vr = tid >> 4, vc = (tid & 15) * 4;

    float acc[2][4][4];
    #pragma unroll
    for (int mt = 0; mt < 2; mt++)
        #pragma unroll
        for (int nt = 0; nt < 4; nt++)
            #pragma unroll
            for (int i = 0; i < 4; i++) acc[mt][nt][i] = 0.f;

    float4 pa[4], pb[2];
    #pragma unroll
    for (int i = 0; i < 4; i++)
        pa[i] = *(const float4*)&Pb[(size_t)(ar + i * 32) * Lseq + ac];
    #pragma unroll
    for (int i = 0; i < 2; i++)
        pb[i] = *(const float4*)&Vb[(size_t)(vr + i * 16) * (3 * Dm) + vc];

    for (int k0 = 0; k0 < Lseq; k0 += 32) {
        #pragma unroll
        for (int i = 0; i < 4; i++)
            *(float4*)&As[ar + i * 32][ac] = tf32r4(pa[i]);
        #pragma unroll
        for (int i = 0; i < 2; i++)
            *(float4*)&Bs[vr + i * 16][vc] = tf32r4(pb[i]);
        __syncthreads();
        if (k0 + 32 < Lseq) {
            #pragma unroll
            for (int i = 0; i < 4; i++)
                pa[i] = *(const float4*)&Pb[(size_t)(ar + i * 32) * Lseq + k0 + 32 + ac];
            #pragma unroll
            for (int i = 0; i < 2; i++)
                pb[i] = *(const float4*)&Vb[(size_t)(k0 + 32 + vr + i * 16) * (3 * Dm) + vc];
        }

        #pragma unroll
        for (int ks = 0; ks < 4; ks++) {
            const int kk = ks * 8;
            float af[2][4], bf[4][2];
            #pragma unroll
            for (int mt = 0; mt < 2; mt++) {
                int r0 = m_base + mt * 16 + gid;
                af[mt][0] = As[r0][kk + tig];
                af[mt][1] = As[r0 + 8][kk + tig];
                af[mt][2] = As[r0][kk + tig + 4];
                af[mt][3] = As[r0 + 8][kk + tig + 4];
            }
            #pragma unroll
            for (int nt = 0; nt < 4; nt++) {
                int c0 = n_base + nt * 8 + gid;
                bf[nt][0] = Bs[kk + tig][c0];
                bf[nt][1] = Bs[kk + tig + 4][c0];
            }
            #pragma unroll
            for (int mt = 0; mt < 2; mt++)
                #pragma unroll
                for (int nt = 0; nt < 4; nt++)
                    mma_tf32(acc[mt][nt], af[mt], bf[nt]);
        }
        __syncthreads();
    }

    #pragma unroll
    for (int mt = 0; mt < 2; mt++) {
        #pragma unroll
        for (int nt = 0; nt < 4; nt++) {
            int col = n_base + nt * 8 + tig * 2;
            #pragma unroll
            for (int half = 0; half < 2; half++) {
                int row = ml + m_base + mt * 16 + gid + half * 8;
                float2 out = make_float2(acc[mt][nt][half * 2 + 0],
                                         acc[mt][nt][half * 2 + 1]);
                *(float2*)&o[(size_t)(b * Lseq + row) * Dm + h * HDd + col] = out;
            }
        }
    }
}

// ---------------------------------------------------------------------------
// Launch sequence (graph-capturable: kernel launches only)
// ---------------------------------------------------------------------------
extern "C" void kernel_launch(void* const* d_in, const int* in_sizes, int n_in,
                              void* d_out, int out_size) {
    const float* spatial   = (const float*)d_in[0];
    const float* density   = (const float*)d_in[1];
    const float* ce        = (const float*)d_in[2];
    const float* spatial_w = (const float*)d_in[3];
    const float* spatial_b = (const float*)d_in[4];
    const float* cond_w    = (const float*)d_in[5];
    const float* cond_b    = (const float*)d_in[6];
    const float* ln1_g     = (const float*)d_in[7];
    const float* ln1_b     = (const float*)d_in[8];
    const float* qkv_w     = (const float*)d_in[9];
    const float* q_scale   = (const float*)d_in[10];
    const float* k_scale   = (const float*)d_in[11];
    const float* proj_w    = (const float*)d_in[12];
    const float* proj_b    = (const float*)d_in[13];
    const float* dscale    = (const float*)d_in[14];
    const float* dbias     = (const float*)d_in[15];
    const float* ln2_g     = (const float*)d_in[16];
    const float* ln2_b     = (const float*)d_in[17];
    const float* mlp_w1    = (const float*)d_in[18];
    const float* mlp_b1    = (const float*)d_in[19];
    const float* mlp_w2    = (const float*)d_in[20];
    const float* mlp_b2    = (const float*)d_in[21];
    const float* out_w     = (const float*)d_in[22];
    const float* out_b     = (const float*)d_in[23];

    float *x, *h, *qkv, *o, *mlp, *cond, *scores;
    cudaGetSymbolAddress((void**)&x,      g_x);
    cudaGetSymbolAddress((void**)&h,      g_h);
    cudaGetSymbolAddress((void**)&qkv,    g_qkv);
    cudaGetSymbolAddress((void**)&o,      g_o);
    cudaGetSymbolAddress((void**)&mlp,    g_mlp);
    cudaGetSymbolAddress((void**)&cond,   g_cond);
    cudaGetSymbolAddress((void**)&scores, g_scores);

    cond_kernel<<<(Bsz * Dm + 255) / 256, 256>>>(ce, cond_w, cond_b, cond);
    mma_gemm<true, false, false, true><<<dim3(Dm / TBN, NTOK / TBM), 256>>>(
        spatial, spatial_w, spatial_b, nullptr, cond, x, NTOK, Dm, Dm);

    for (int i = 0; i < NLn; i++) {
        layernorm_kernel<<<NTOK, 256>>>(x, ln1_g + i * Dm, ln1_b + i * Dm, h);

        mma_gemm<false, false, false, false>
            <<<dim3(3 * Dm / TBN, NTOK / TBM), 256>>>(
            h, qkv_w + (size_t)i * Dm * 3 * Dm, nullptr, nullptr, nullptr,
            qkv, NTOK, 3 * Dm, Dm);

        rmsrope_kernel<<<NTOK, 768>>>(qkv, q_scale + i * HDd, k_scale + i * HDd);

        scores_mma<<<dim3(Lseq / 128, Lseq / 128, NBH), 256>>>(
            qkv, density, dscale, dbias, i, scores);
        softmax_kernel<<<NBH * Lseq, 256>>>(scores);
        pv_mma<<<dim3(Lseq / 128, NBH), 256>>>(scores, qkv, o);

        mma_gemm<true, false, true, false>
            <<<dim3(Dm / TBN, NTOK / TBM), 256>>>(
            o, proj_w + (size_t)i * Dm * Dm, proj_b + i * Dm, x, nullptr,
            x, NTOK, Dm, Dm);

        layernorm_kernel<<<NTOK, 256>>>(x, ln2_g + i * Dm, ln2_b + i * Dm, h);

        mma_gemm<true, true, false, false>
            <<<dim3(MLPd / TBN, NTOK / TBM), 256>>>(
            h, mlp_w1 + (size_t)i * Dm * MLPd, mlp_b1 + i * MLPd, nullptr,
            nullptr, mlp, NTOK, MLPd, Dm);

        mma_gemm<true, false, true, false>
            <<<dim3(Dm / TBN, NTOK / TBM), 256>>>(
            mlp, mlp_w2 + (size_t)i * MLPd * Dm, mlp_b2 + i * Dm, x, nullptr,
            x, NTOK, Dm, MLPd);
    }

    mma_gemm<true, false, false, false>
        <<<dim3(Dm / TBN, NTOK / TBM), 256>>>(
        x, out_w, out_b, nullptr, nullptr, (float*)d_out, NTOK, Dm, Dm);
}

// round 10
// speedup vs baseline: 2.2965x; 1.1105x over previous
#include <cuda_runtime.h>
#include <cuda_bf16.h>
#include <stdint.h>
#include <math.h>

// Problem constants
#define Bsz  2
#define Lseq 1024
#define Dm   768
#define NHn  12
#define HDd  64
#define NLn  6
#define MLPd 3072
#define NTOK (Bsz * Lseq)   // 2048
#define NBH  (Bsz * NHn)    // 24

// TF32 rounding (round-to-nearest, matches cuBLAS input conversion)
__device__ __forceinline__ float tf32r(float x) {
    asm("cvt.rna.tf32.f32 %0, %0;" : "+f"(x));
    return x;
}
__device__ __forceinline__ float4 tf32r4(float4 v) {
    v.x = tf32r(v.x); v.y = tf32r(v.y); v.z = tf32r(v.z); v.w = tf32r(v.w);
    return v;
}

// m16n8k8 tf32 mma, fp32 accumulate
__device__ __forceinline__ void mma_tf32(float* c, const float* a, const float* b) {
    asm volatile(
        "mma.sync.aligned.m16n8k8.row.col.f32.tf32.tf32.f32 "
        "{%0,%1,%2,%3}, {%4,%5,%6,%7}, {%8,%9}, {%0,%1,%2,%3};\n"
        : "+f"(c[0]), "+f"(c[1]), "+f"(c[2]), "+f"(c[3])
        : "r"(__float_as_uint(a[0])), "r"(__float_as_uint(a[1])),
          "r"(__float_as_uint(a[2])), "r"(__float_as_uint(a[3])),
          "r"(__float_as_uint(b[0])), "r"(__float_as_uint(b[1])));
}

// cp.async helpers
__device__ __forceinline__ void cp16(uint32_t s, const void* g) {
    asm volatile("cp.async.cg.shared.global [%0], [%1], 16;\n" :: "r"(s), "l"(g));
}
#define CP_COMMIT() asm volatile("cp.async.commit_group;\n")
#define CP_WAIT1()  asm volatile("cp.async.wait_group 1;\n")
#define CP_WAIT0()  asm volatile("cp.async.wait_group 0;\n")

// ---------------------------------------------------------------------------
// Scratch (static device globals; no allocation)
// ---------------------------------------------------------------------------
__device__ float g_x     [NTOK * Dm];
__device__ float g_h     [NTOK * Dm];        // LN out (rounded); reused for rounded final x
__device__ float g_qkv   [NTOK * 3 * Dm];
__device__ float g_o     [NTOK * Dm];
__device__ float g_mlp   [NTOK * MLPd];      // also holds rounded spatial at layer 0
__device__ float g_cond  [Bsz * Dm];
__device__ float g_scores[(size_t)NBH * Lseq * Lseq];   // 100.7 MB
// pre-rounded weight copies
__device__ float g_wspat [Dm * Dm];
__device__ float g_wqkv  [NLn * Dm * 3 * Dm];
__device__ float g_wproj [NLn * Dm * Dm];
__device__ float g_wm1   [NLn * Dm * MLPd];
__device__ float g_wm2   [NLn * MLPd * Dm];
__device__ float g_wout  [Dm * Dm];

// ---------------------------------------------------------------------------
// Elementwise tf32 round-copy (float4), n4 = n/4
// ---------------------------------------------------------------------------
__global__ void round_kernel(const float* __restrict__ src, float* __restrict__ dst,
                             int n4) {
    int i = blockIdx.x * blockDim.x + threadIdx.x;
    if (i < n4) ((float4*)dst)[i] = tf32r4(((const float4*)src)[i]);
}

// ---------------------------------------------------------------------------
// cond_out[b,n] = ce[b,:] @ cond_w[:,n] + cond_b[n]   (exact fp32, tiny)
// ---------------------------------------------------------------------------
__global__ void cond_kernel(const float* __restrict__ ce,
                            const float* __restrict__ w,
                            const float* __restrict__ cb,
                            float* __restrict__ out) {
    int idx = blockIdx.x * blockDim.x + threadIdx.x;
    if (idx >= Bsz * Dm) return;
    int b = idx / Dm, n = idx % Dm;
    float s = 0.f;
    const float* cer = ce + b * 1536;
    #pragma unroll 4
    for (int k = 0; k < 1536; k++) s += cer[k] * w[k * Dm + n];
    out[idx] = s + cb[n];
}

// ---------------------------------------------------------------------------
// TF32 tensor-core GEMM, cp.async double-buffered. Inputs PRE-ROUNDED to tf32.
// C[M,N] = A[M,K] @ B[K,N] (+bias +cond +gelu +res)
// Tiles 128x128x32, 256 threads = 8 warps (4m x 2n), 2 blocks/SM.
// ---------------------------------------------------------------------------
#define TBM 128
#define TBN 128
#define TBK 32
#define ASTR 36
#define BSTR 132
#define ABUF (128 * ASTR)                 // floats per A stage
#define BBUF (32 * BSTR)                  // floats per B stage
#define GEMM_DSMEM (2 * (ABUF + BBUF) * 4)   // 70656 bytes

template<bool BIAS, bool GELU_F, bool RES, bool COND>
__global__ __launch_bounds__(256, 2)
void mma_gemm(const float* __restrict__ A, const float* __restrict__ Bm,
              const float* __restrict__ bias, const float* __restrict__ res,
              const float* __restrict__ cond, float* __restrict__ C,
              int M, int N, int K) {
    extern __shared__ float dsm[];
    float* AsB = dsm;                 // [2][128][ASTR]
    float* BsB = dsm + 2 * ABUF;      // [2][32][BSTR]
    const uint32_t aS = (uint32_t)__cvta_generic_to_shared(AsB);
    const uint32_t bS = (uint32_t)__cvta_generic_to_shared(BsB);

    const int tid  = threadIdx.x;
    const int bm   = blockIdx.y * TBM;
    const int bn   = blockIdx.x * TBN;
    const int warp = tid >> 5, lane = tid & 31;
    const int wm = warp >> 1, wn = warp & 1;
    const int gid = lane >> 2, tig = lane & 3;
    const int m_base = wm * 32, n_base = wn * 64;

    const int ar = tid >> 3;             // 0..31 (+i*32)
    const int ac = (tid & 7) * 4;        // 0..28
    const int br = tid >> 3;             // 0..31
    const int bc = (tid & 7) * 16;       // +i*4

    float acc[2][8][4];
    #pragma unroll
    for (int mt = 0; mt < 2; mt++)
        #pragma unroll
        for (int nt = 0; nt < 8; nt++)
            #pragma unroll
            for (int i = 0; i < 4; i++) acc[mt][nt][i] = 0.f;

    const int nk = K / TBK;

    // prologue stage 0
    {
        uint32_t ab = aS;
        uint32_t bb = bS;
        #pragma unroll
        for (int i = 0; i < 4; i++)
            cp16(ab + (uint32_t)((ar + i * 32) * ASTR + ac) * 4,
                 &A[(size_t)(bm + ar + i * 32) * K + ac]);
        #pragma unroll
        for (int i = 0; i < 4; i++)
            cp16(bb + (uint32_t)(br * BSTR + bc + i * 4) * 4,
                 &Bm[(size_t)br * N + bn + bc + i * 4]);
        CP_COMMIT();
    }

    for (int kc = 0; kc < nk; kc++) {
        const int cur = kc & 1;
        if (kc + 1 < nk) {
            const int k0 = (kc + 1) * TBK;
            uint32_t ab = aS + (uint32_t)((cur ^ 1) * ABUF) * 4;
            uint32_t bb = bS + (uint32_t)((cur ^ 1) * BBUF) * 4;
            #pragma unroll
            for (int i = 0; i < 4; i++)
                cp16(ab + (uint32_t)((ar + i * 32) * ASTR + ac) * 4,
                     &A[(size_t)(bm + ar + i * 32) * K + k0 + ac]);
            #pragma unroll
            for (int i = 0; i < 4; i++)
                cp16(bb + (uint32_t)(br * BSTR + bc + i * 4) * 4,
                     &Bm[(size_t)(k0 + br) * N + bn + bc + i * 4]);
            CP_COMMIT();
            CP_WAIT1();
        } else {
            CP_WAIT0();
        }
        __syncthreads();

        const float* As = AsB + cur * ABUF;
        const float* Bs = BsB + cur * BBUF;
        #pragma unroll
        for (int ks = 0; ks < 4; ks++) {
            const int kk = ks * 8;
            float af[2][4], bf[8][2];
            #pragma unroll
            for (int mt = 0; mt < 2; mt++) {
                int r0 = m_base + mt * 16 + gid;
                af[mt][0] = As[r0 * ASTR + kk + tig];
                af[mt][1] = As[(r0 + 8) * ASTR + kk + tig];
                af[mt][2] = As[r0 * ASTR + kk + tig + 4];
                af[mt][3] = As[(r0 + 8) * ASTR + kk + tig + 4];
            }
            #pragma unroll
            for (int nt = 0; nt < 8; nt++) {
                int c0 = n_base + nt * 8 + gid;
                bf[nt][0] = Bs[(kk + tig) * BSTR + c0];
                bf[nt][1] = Bs[(kk + tig + 4) * BSTR + c0];
            }
            #pragma unroll
            for (int mt = 0; mt < 2; mt++)
                #pragma unroll
                for (int nt = 0; nt < 8; nt++)
                    mma_tf32(acc[mt][nt], af[mt], bf[nt]);
        }
        __syncthreads();
    }

    #pragma unroll
    for (int mt = 0; mt < 2; mt++) {
        #pragma unroll
        for (int nt = 0; nt < 8; nt++) {
            int col = bn + n_base + nt * 8 + tig * 2;
            #pragma unroll
            for (int half = 0; half < 2; half++) {
                int row = bm + m_base + mt * 16 + gid + half * 8;
                float vx = acc[mt][nt][half * 2 + 0];
                float vy = acc[mt][nt][half * 2 + 1];
                if (BIAS) { vx += bias[col]; vy += bias[col + 1]; }
                if (COND) {
                    const float* cp = cond + (row >> 10) * N + col;
                    vx += cp[0]; vy += cp[1];
                }
                if (GELU_F) {
                    vx = 0.5f * vx * (1.f + erff(vx * 0.70710678118654752f));
                    vy = 0.5f * vy * (1.f + erff(vy * 0.70710678118654752f));
                    vx = tf32r(vx); vy = tf32r(vy);   // mlp buffer feeds next GEMM
                }
                if (RES) {
                    float2 rr = *(const float2*)&res[(size_t)row * N + col];
                    vx += rr.x; vy += rr.y;
                }
                float2 out = make_float2(vx, vy);
                *(float2*)&C[(size_t)row * N + col] = out;
            }
        }
    }
}

// ---------------------------------------------------------------------------
// LayerNorm: one block per token row; output rounded to tf32 (GEMM-A only).
// ---------------------------------------------------------------------------
__global__ __launch_bounds__(256)
void layernorm_kernel(const float* __restrict__ x, const float* __restrict__ g,
                      const float* __restrict__ b, float* __restrict__ out) {
    int row = blockIdx.x;
    int t = threadIdx.x;
    const float* xr = x + (size_t)row * Dm;
    float v0 = xr[t], v1 = xr[t + 256], v2 = xr[t + 512];
    float s = v0 + v1 + v2;
    float q = v0 * v0 + v1 * v1 + v2 * v2;
    #pragma unroll
    for (int o = 16; o > 0; o >>= 1) {
        s += __shfl_xor_sync(0xffffffffu, s, o);
        q += __shfl_xor_sync(0xffffffffu, q, o);
    }
    __shared__ float ss[8], sq[8];
    int wid = t >> 5, lane = t & 31;
    if (!lane) { ss[wid] = s; sq[wid] = q; }
    __syncthreads();
    if (t == 0) {
        float S = 0.f, Q = 0.f;
        #pragma unroll
        for (int i = 0; i < 8; i++) { S += ss[i]; Q += sq[i]; }
        float m = S * (1.f / Dm);
        float var = Q * (1.f / Dm) - m * m;
        ss[0] = m;
        sq[0] = rsqrtf(var + 1e-5f);
    }
    __syncthreads();
    float m = ss[0], r = sq[0];
    float* orow = out + (size_t)row * Dm;
    orow[t]       = tf32r((v0 - m) * r * g[t]       + b[t]);
    orow[t + 256] = tf32r((v1 - m) * r * g[t + 256] + b[t + 256]);
    orow[t + 512] = tf32r((v2 - m) * r * g[t + 512] + b[t + 512]);
}

// ---------------------------------------------------------------------------
// Fused RMSNorm + RoPE on q,k (rounded outputs) + round v in place.
// ---------------------------------------------------------------------------
__global__ __launch_bounds__(768)
void rmsrope_kernel(float* __restrict__ qkv,
                    const float* __restrict__ qs,
                    const float* __restrict__ ks) {
    int token = blockIdx.x;
    int w = threadIdx.x >> 5;
    int lane = threadIdx.x & 31;
    int isK = (w >= NHn);
    int h = isK ? w - NHn : w;
    float* base = qkv + (size_t)token * (3 * Dm) + (isK ? Dm : 0) + h * HDd;
    const float* sc = isK ? ks : qs;

    float x0 = base[2 * lane], x1 = base[2 * lane + 1];
    float s = x0 * x0 + x1 * x1;
    #pragma unroll
    for (int o = 16; o > 0; o >>= 1) s += __shfl_xor_sync(0xffffffffu, s, o);
    float r = rsqrtf(s * (1.f / HDd) + 1e-6f);
    float y0 = x0 * r * sc[2 * lane];
    float y1 = x1 * r * sc[2 * lane + 1];

    int l = token & (Lseq - 1);
    int col = l & 31, rowp = l >> 5;
    double pos, fidx;
    if (lane < 16) { pos = (double)col;  fidx = (double)lane; }
    else           { pos = (double)rowp; fidx = (double)(lane - 16); }
    double omega = exp(fidx * -0.5756462732485115);
    double ang = pos * omega;
    float c  = (float)cos(ang);
    float sn = (float)sin(ang);
    base[2 * lane]     = tf32r(c * y0 - sn * y1);
    base[2 * lane + 1] = tf32r(sn * y0 + c * y1);

    // round v (used only by pv GEMM)
    float* vb = qkv + (size_t)token * (3 * Dm) + 2 * Dm;
    vb[threadIdx.x] = tf32r(vb[threadIdx.x]);
}

// ---------------------------------------------------------------------------
// Scores via tf32 mma (q,k pre-rounded): S = (q.k)*0.125 + density bias
// ---------------------------------------------------------------------------
__global__ __launch_bounds__(256)
void scores_mma(const float* __restrict__ qkv, const float* __restrict__ dens,
                const float* __restrict__ dscale, const float* __restrict__ dbias,
                int layer, float* __restrict__ S) {
    __shared__ float As[128][36];
    __shared__ float Bs[32][132];

    const int tid  = threadIdx.x;
    const int mkey = blockIdx.x * 128;
    const int mq   = blockIdx.y * 128;
    const int z    = blockIdx.z;
    const int b = z / NHn, h = z % NHn;
    const int warp = tid >> 5, lane = tid & 31;
    const int wm = warp >> 1, wn = warp & 1;
    const int gid = lane >> 2, tig = lane & 3;
    const int m_base = wm * 32, n_base = wn * 64;

    const float* Qb = qkv + (size_t)(b * Lseq + mq) * (3 * Dm) + h * HDd;
    const float* Kb = qkv + (size_t)(b * Lseq + mkey) * (3 * Dm) + Dm + h * HDd;

    const int ar = tid >> 3, ac = (tid & 7) * 4;
    const int key = tid >> 1, d4b = (tid & 1) * 4;

    float acc[2][8][4];
    #pragma unroll
    for (int mt = 0; mt < 2; mt++)
        #pragma unroll
        for (int nt = 0; nt < 8; nt++)
            #pragma unroll
            for (int i = 0; i < 4; i++) acc[mt][nt][i] = 0.f;

    float4 pa[4], pb[4];
    #pragma unroll
    for (int i = 0; i < 4; i++) {
        pa[i] = *(const float4*)&Qb[(size_t)(ar + i * 32) * (3 * Dm) + ac];
        pb[i] = *(const float4*)&Kb[(size_t)key * (3 * Dm) + d4b + i * 8];
    }

    for (int k0 = 0; k0 < HDd; k0 += 32) {
        #pragma unroll
        for (int i = 0; i < 4; i++) {
            *(float4*)&As[ar + i * 32][ac] = pa[i];
            int d4 = d4b + i * 8;
            Bs[d4 + 0][key] = pb[i].x;
            Bs[d4 + 1][key] = pb[i].y;
            Bs[d4 + 2][key] = pb[i].z;
            Bs[d4 + 3][key] = pb[i].w;
        }
        __syncthreads();
        if (k0 + 32 < HDd) {
            #pragma unroll
            for (int i = 0; i < 4; i++) {
                pa[i] = *(const float4*)&Qb[(size_t)(ar + i * 32) * (3 * Dm) + k0 + 32 + ac];
                pb[i] = *(const float4*)&Kb[(size_t)key * (3 * Dm) + k0 + 32 + d4b + i * 8];
            }
        }

        #pragma unroll
        for (int ks = 0; ks < 4; ks++) {
            const int kk = ks * 8;
            float af[2][4], bf[8][2];
            #pragma unroll
            for (int mt = 0; mt < 2; mt++) {
                int r0 = m_base + mt * 16 + gid;
                af[mt][0] = As[r0][kk + tig];
                af[mt][1] = As[r0 + 8][kk + tig];
                af[mt][2] = As[r0][kk + tig + 4];
                af[mt][3] = As[r0 + 8][kk + tig + 4];
            }
            #pragma unroll
            for (int nt = 0; nt < 8; nt++) {
                int c0 = n_base + nt * 8 + gid;
                bf[nt][0] = Bs[kk + tig][c0];
                bf[nt][1] = Bs[kk + tig + 4][c0];
            }
            #pragma unroll
            for (int mt = 0; mt < 2; mt++)
                #pragma unroll
                for (int nt = 0; nt < 8; nt++)
                    mma_tf32(acc[mt][nt], af[mt], bf[nt]);
        }
        __syncthreads();
    }

    const float dsc = dscale[layer], dbi = dbias[layer];
    #pragma unroll
    for (int mt = 0; mt < 2; mt++) {
        #pragma unroll
        for (int nt = 0; nt < 8; nt++) {
            int col = mkey + n_base + nt * 8 + tig * 2;
            #pragma unroll
            for (int half = 0; half < 2; half++) {
                int row = mq + m_base + mt * 16 + gid + half * 8;
                float bv = dsc * dens[b * Lseq + row] + dbi;
                float2 out = make_float2(
                    acc[mt][nt][half * 2 + 0] * 0.125f + bv,
                    acc[mt][nt][half * 2 + 1] * 0.125f + bv);
                *(float2*)&S[((size_t)z * Lseq + row) * Lseq + col] = out;
            }
        }
    }
}

// ---------------------------------------------------------------------------
// Exact row softmax over 1024 keys, in place; output rounded (feeds pv only).
// ---------------------------------------------------------------------------
__global__ __launch_bounds__(256)
void softmax_kernel(float* __restrict__ S) {
    const int t = threadIdx.x;
    float* p = S + (size_t)blockIdx.x * Lseq;
    float v[4];
    #pragma unroll
    for (int i = 0; i < 4; i++) v[i] = p[t + i * 256];

    float m = fmaxf(fmaxf(v[0], v[1]), fmaxf(v[2], v[3]));
    #pragma unroll
    for (int o = 16; o > 0; o >>= 1) m = fmaxf(m, __shfl_xor_sync(0xffffffffu, m, o));
    __shared__ float sm[8];
    int wid = t >> 5, lane = t & 31;
    if (!lane) sm[wid] = m;
    __syncthreads();
    if (t == 0) {
        float M = sm[0];
        #pragma unroll
        for (int i = 1; i < 8; i++) M = fmaxf(M, sm[i]);
        sm[0] = M;
    }
    __syncthreads();
    m = sm[0];

    float e[4], s = 0.f;
    #pragma unroll
    for (int i = 0; i < 4; i++) { e[i] = expf(v[i] - m); s += e[i]; }
    #pragma unroll
    for (int o = 16; o > 0; o >>= 1) s += __shfl_xor_sync(0xffffffffu, s, o);
    __shared__ float sq[8];
    if (!lane) sq[wid] = s;
    __syncthreads();
    if (t == 0) {
        float Ssum = 0.f;
        #pragma unroll
        for (int i = 0; i < 8; i++) Ssum += sq[i];
        sq[0] = Ssum;
    }
    __syncthreads();
    s = sq[0];
    #pragma unroll
    for (int i = 0; i < 4; i++) p[t + i * 256] = tf32r(e[i] / s);
}

// ---------------------------------------------------------------------------
// PV via tf32 mma, cp.async double-buffered (P, V pre-rounded).
// M=128 l, N=64 d, K=1024 m. Output o rounded (feeds proj GEMM only).
// ---------------------------------------------------------------------------
#define PASTR 36
#define PBSTR 68
#define PABUF (128 * PASTR)   // 4608
#define PBBUF (32 * PBSTR)    // 2176
#define PV_DSMEM (2 * (PABUF + PBBUF) * 4)   // 54272 bytes

__global__ __launch_bounds__(256, 2)
void pv_mma(const float* __restrict__ S, const float* __restrict__ qkv,
            float* __restrict__ o) {
    extern __shared__ float dsm[];
    float* AsB = dsm;
    float* BsB = dsm + 2 * PABUF;
    const uint32_t aS = (uint32_t)__cvta_generic_to_shared(AsB);
    const uint32_t bS = (uint32_t)__cvta_generic_to_shared(BsB);

    const int tid = threadIdx.x;
    const int ml  = blockIdx.x * 128;
    const int z   = blockIdx.y;
    const int b = z / NHn, h = z % NHn;
    const int warp = tid >> 5, lane = tid & 31;
    const int wm = warp >> 1, wn = warp & 1;
    const int gid = lane >> 2, tig = lane & 3;
    const int m_base = wm * 32, n_base = wn * 32;

    const float* Pb = S + ((size_t)z * Lseq + ml) * Lseq;
    const float* Vb = qkv + (size_t)(b * Lseq) * (3 * Dm) + 2 * Dm + h * HDd;

    const int ar = tid >> 3, ac = (tid & 7) * 4;
    const int vr = tid >> 4, vc = (tid & 15) * 4;

    float acc[2][4][4];
    #pragma unroll
    for (int mt = 0; mt < 2; mt++)
        #pragma unroll
        for (int nt = 0; nt < 4; nt++)
            #pragma unroll
            for (int i = 0; i < 4; i++) acc[mt][nt][i] = 0.f;

    const int nk = Lseq / 32;

    // prologue stage 0
    {
        #pragma unroll
        for (int i = 0; i < 4; i++)
            cp16(aS + (uint32_t)((ar + i * 32) * PASTR + ac) * 4,
                 &Pb[(size_t)(ar + i * 32) * Lseq + ac]);
        #pragma unroll
        for (int i = 0; i < 2; i++)
            cp16(bS + (uint32_t)((vr + i * 16) * PBSTR + vc) * 4,
                 &Vb[(size_t)(vr + i * 16) * (3 * Dm) + vc]);
        CP_COMMIT();
    }

    for (int kc = 0; kc < nk; kc++) {
        const int cur = kc & 1;
        if (kc + 1 < nk) {
            const int k0 = (kc + 1) * 32;
            uint32_t ab = aS + (uint32_t)((cur ^ 1) * PABUF) * 4;
            uint32_t bb = bS + (uint32_t)((cur ^ 1) * PBBUF) * 4;
            #pragma unroll
            for (int i = 0; i < 4; i++)
                cp16(ab + (uint32_t)((ar + i * 32) * PASTR + ac) * 4,
                     &Pb[(size_t)(ar + i * 32) * Lseq + k0 + ac]);
            #pragma unroll
            for (int i = 0; i < 2; i++)
                cp16(bb + (uint32_t)((vr + i * 16) * PBSTR + vc) * 4,
                     &Vb[(size_t)(k0 + vr + i * 16) * (3 * Dm) + vc]);
            CP_COMMIT();
            CP_WAIT1();
        } else {
            CP_WAIT0();
        }
        __syncthreads();

        const float* As = AsB + cur * PABUF;
        const float* Bs = BsB + cur * PBBUF;
        #pragma unroll
        for (int ks = 0; ks < 4; ks++) {
            const int kk = ks * 8;
            float af[2][4], bf[4][2];
            #pragma unroll
            for (int mt = 0; mt < 2; mt++) {
                int r0 = m_base + mt * 16 + gid;
                af[mt][0] = As[r0 * PASTR + kk + tig];
                af[mt][1] = As[(r0 + 8) * PASTR + kk + tig];
                af[mt][2] = As[r0 * PASTR + kk + tig + 4];
                af[mt][3] = As[(r0 + 8) * PASTR + kk + tig + 4];
            }
            #pragma unroll
            for (int nt = 0; nt < 4; nt++) {
                int c0 = n_base + nt * 8 + gid;
                bf[nt][0] = Bs[(kk + tig) * PBSTR + c0];
                bf[nt][1] = Bs[(kk + tig + 4) * PBSTR + c0];
            }
            #pragma unroll
            for (int mt = 0; mt < 2; mt++)
                #pragma unroll
                for (int nt = 0; nt < 4; nt++)
                    mma_tf32(acc[mt][nt], af[mt], bf[nt]);
        }
        __syncthreads();
    }

    #pragma unroll
    for (int mt = 0; mt < 2; mt++) {
        #pragma unroll
        for (int nt = 0; nt < 4; nt++) {
            int col = n_base + nt * 8 + tig * 2;
            #pragma unroll
            for (int half = 0; half < 2; half++) {
                int row = ml + m_base + mt * 16 + gid + half * 8;
                float2 out = make_float2(tf32r(acc[mt][nt][half * 2 + 0]),
                                         tf32r(acc[mt][nt][half * 2 + 1]));
                *(float2*)&o[(size_t)(b * Lseq + row) * Dm + h * HDd + col] = out;
            }
        }
    }
}

// ---------------------------------------------------------------------------
// Launch sequence (graph-capturable: kernel launches only)
// ---------------------------------------------------------------------------
extern "C" void kernel_launch(void* const* d_in, const int* in_sizes, int n_in,
                              void* d_out, int out_size) {
    const float* spatial   = (const float*)d_in[0];
    const float* density   = (const float*)d_in[1];
    const float* ce        = (const float*)d_in[2];
    const float* spatial_w = (const float*)d_in[3];
    const float* spatial_b = (const float*)d_in[4];
    const float* cond_w    = (const float*)d_in[5];
    const float* cond_b    = (const float*)d_in[6];
    const float* ln1_g     = (const float*)d_in[7];
    const float* ln1_b     = (const float*)d_in[8];
    const float* qkv_w     = (const float*)d_in[9];
    const float* q_scale   = (const float*)d_in[10];
    const float* k_scale   = (const float*)d_in[11];
    const float* proj_w    = (const float*)d_in[12];
    const float* proj_b    = (const float*)d_in[13];
    const float* dscale    = (const float*)d_in[14];
    const float* dbias     = (const float*)d_in[15];
    const float* ln2_g     = (const float*)d_in[16];
    const float* ln2_b     = (const float*)d_in[17];
    const float* mlp_w1    = (const float*)d_in[18];
    const float* mlp_b1    = (const float*)d_in[19];
    const float* mlp_w2    = (const float*)d_in[20];
    const float* mlp_b2    = (const float*)d_in[21];
    const float* out_w     = (const float*)d_in[22];
    const float* out_b     = (const float*)d_in[23];

    float *x, *h, *qkv, *o, *mlp, *cond, *scores;
    float *wspat, *wqkv, *wproj, *wm1, *wm2, *wout;
    cudaGetSymbolAddress((void**)&x,      g_x);
    cudaGetSymbolAddress((void**)&h,      g_h);
    cudaGetSymbolAddress((void**)&qkv,    g_qkv);
    cudaGetSymbolAddress((void**)&o,      g_o);
    cudaGetSymbolAddress((void**)&mlp,    g_mlp);
    cudaGetSymbolAddress((void**)&cond,   g_cond);
    cudaGetSymbolAddress((void**)&scores, g_scores);
    cudaGetSymbolAddress((void**)&wspat,  g_wspat);
    cudaGetSymbolAddress((void**)&wqkv,   g_wqkv);
    cudaGetSymbolAddress((void**)&wproj,  g_wproj);
    cudaGetSymbolAddress((void**)&wm1,    g_wm1);
    cudaGetSymbolAddress((void**)&wm2,    g_wm2);
    cudaGetSymbolAddress((void**)&wout,   g_wout);

    // allow >48KB dynamic smem
    cudaFuncSetAttribute(mma_gemm<true,  false, false, true >, cudaFuncAttributeMaxDynamicSharedMemorySize, GEMM_DSMEM);
    cudaFuncSetAttribute(mma_gemm<false, false, false, false>, cudaFuncAttributeMaxDynamicSharedMemorySize, GEMM_DSMEM);
    cudaFuncSetAttribute(mma_gemm<true,  false, true,  false>, cudaFuncAttributeMaxDynamicSharedMemorySize, GEMM_DSMEM);
    cudaFuncSetAttribute(mma_gemm<true,  true,  false, false>, cudaFuncAttributeMaxDynamicSharedMemorySize, GEMM_DSMEM);
    cudaFuncSetAttribute(mma_gemm<true,  false, false, false>, cudaFuncAttributeMaxDynamicSharedMemorySize, GEMM_DSMEM);
    cudaFuncSetAttribute(pv_mma, cudaFuncAttributeMaxDynamicSharedMemorySize, PV_DSMEM);

    // pre-round weights + spatial input (elementwise, position-independent)
    round_kernel<<<(Dm * Dm / 4 + 255) / 256, 256>>>(spatial_w, wspat, Dm * Dm / 4);
    round_kernel<<<(NLn * Dm * 3 * Dm / 4 + 255) / 256, 256>>>(qkv_w, wqkv, NLn * Dm * 3 * Dm / 4);
    round_kernel<<<(NLn * Dm * Dm / 4 + 255) / 256, 256>>>(proj_w, wproj, NLn * Dm * Dm / 4);
    round_kernel<<<(NLn * Dm * MLPd / 4 + 255) / 256, 256>>>(mlp_w1, wm1, NLn * Dm * MLPd / 4);
    round_kernel<<<(NLn * MLPd * Dm / 4 + 255) / 256, 256>>>(mlp_w2, wm2, NLn * MLPd * Dm / 4);
    round_kernel<<<(Dm * Dm / 4 + 255) / 256, 256>>>(out_w, wout, Dm * Dm / 4);
    round_kernel<<<(NTOK * Dm / 4 + 255) / 256, 256>>>(spatial, mlp, NTOK * Dm / 4);

    cond_kernel<<<(Bsz * Dm + 255) / 256, 256>>>(ce, cond_w, cond_b, cond);
    mma_gemm<true, false, false, true>
        <<<dim3(Dm / TBN, NTOK / TBM), 256, GEMM_DSMEM>>>(
        mlp, wspat, spatial_b, nullptr, cond, x, NTOK, Dm, Dm);

    for (int i = 0; i < NLn; i++) {
        layernorm_kernel<<<NTOK, 256>>>(x, ln1_g + i * Dm, ln1_b + i * Dm, h);

        mma_gemm<false, false, false, false>
            <<<dim3(3 * Dm / TBN, NTOK / TBM), 256, GEMM_DSMEM>>>(
            h, wqkv + (size_t)i * Dm * 3 * Dm, nullptr, nullptr, nullptr,
            qkv, NTOK, 3 * Dm, Dm);

        rmsrope_kernel<<<NTOK, 768>>>(qkv, q_scale + i * HDd, k_scale + i * HDd);

        scores_mma<<<dim3(Lseq / 128, Lseq / 128, NBH), 256>>>(
            qkv, density, dscale, dbias, i, scores);
        softmax_kernel<<<NBH * Lseq, 256>>>(scores);
        pv_mma<<<dim3(Lseq / 128, NBH), 256, PV_DSMEM>>>(scores, qkv, o);

        mma_gemm<true, false, true, false>
            <<<dim3(Dm / TBN, NTOK / TBM), 256, GEMM_DSMEM>>>(
            o, wproj + (size_t)i * Dm * Dm, proj_b + i * Dm, x, nullptr,
            x, NTOK, Dm, Dm);

        layernorm_kernel<<<NTOK, 256>>>(x, ln2_g + i * Dm, ln2_b + i * Dm, h);

        mma_gemm<true, true, false, false>
            <<<dim3(MLPd / TBN, NTOK / TBM), 256, GEMM_DSMEM>>>(
            h, wm1 + (size_t)i * Dm * MLPd, mlp_b1 + i * MLPd, nullptr,
            nullptr, mlp, NTOK, MLPd, Dm);

        mma_gemm<true, false, true, false>
            <<<dim3(Dm / TBN, NTOK / TBM), 256, GEMM_DSMEM>>>(
            mlp, wm2 + (size_t)i * MLPd * Dm, mlp_b2 + i * Dm, x, nullptr,
            x, NTOK, Dm, MLPd);
    }

    // rounded copy of x for the final GEMM (x itself must stay exact)
    round_kernel<<<(NTOK * Dm / 4 + 255) / 256, 256>>>(x, h, NTOK * Dm / 4);
    mma_gemm<true, false, false, false>
        <<<dim3(Dm / TBN, NTOK / TBM), 256, GEMM_DSMEM>>>(
        h, wout, out_b, nullptr, nullptr, (float*)d_out, NTOK, Dm, Dm);
}

// round 12
// speedup vs baseline: 2.3586x; 1.0270x over previous
#include <cuda_runtime.h>
#include <cuda_bf16.h>
#include <stdint.h>
#include <math.h>

// Problem constants
#define Bsz  2
#define Lseq 1024
#define Dm   768
#define NHn  12
#define HDd  64
#define NLn  6
#define MLPd 3072
#define NTOK (Bsz * Lseq)   // 2048
#define NBH  (Bsz * NHn)    // 24

// TF32 rounding (round-to-nearest, matches cuBLAS input conversion)
__device__ __forceinline__ float tf32r(float x) {
    asm("cvt.rna.tf32.f32 %0, %0;" : "+f"(x));
    return x;
}
__device__ __forceinline__ float4 tf32r4(float4 v) {
    v.x = tf32r(v.x); v.y = tf32r(v.y); v.z = tf32r(v.z); v.w = tf32r(v.w);
    return v;
}

// m16n8k8 tf32 mma, fp32 accumulate
__device__ __forceinline__ void mma_tf32(float* c, const float* a, const float* b) {
    asm volatile(
        "mma.sync.aligned.m16n8k8.row.col.f32.tf32.tf32.f32 "
        "{%0,%1,%2,%3}, {%4,%5,%6,%7}, {%8,%9}, {%0,%1,%2,%3};\n"
        : "+f"(c[0]), "+f"(c[1]), "+f"(c[2]), "+f"(c[3])
        : "r"(__float_as_uint(a[0])), "r"(__float_as_uint(a[1])),
          "r"(__float_as_uint(a[2])), "r"(__float_as_uint(a[3])),
          "r"(__float_as_uint(b[0])), "r"(__float_as_uint(b[1])));
}

// cp.async helpers
__device__ __forceinline__ void cp16(uint32_t s, const void* g) {
    asm volatile("cp.async.cg.shared.global [%0], [%1], 16;\n" :: "r"(s), "l"(g));
}
#define CP_COMMIT() asm volatile("cp.async.commit_group;\n")
#define CP_WAIT1()  asm volatile("cp.async.wait_group 1;\n")
#define CP_WAIT0()  asm volatile("cp.async.wait_group 0;\n")

// ---------------------------------------------------------------------------
// Scratch (static device globals; no allocation)
// ---------------------------------------------------------------------------
__device__ float g_x     [NTOK * Dm];
__device__ float g_h     [NTOK * Dm];        // LN out (rounded); rounded final x
__device__ float g_qkv   [NTOK * 3 * Dm];
__device__ float g_o     [NTOK * Dm];
__device__ float g_mlp   [NTOK * MLPd];      // also rounded spatial at layer 0
__device__ float g_cond  [Bsz * Dm];
// pre-rounded weight copies
__device__ float g_wspat [Dm * Dm];
__device__ float g_wqkv  [NLn * Dm * 3 * Dm];
__device__ float g_wproj [NLn * Dm * Dm];
__device__ float g_wm1   [NLn * Dm * MLPd];
__device__ float g_wm2   [NLn * MLPd * Dm];
__device__ float g_wout  [Dm * Dm];

// ---------------------------------------------------------------------------
// Elementwise tf32 round-copy (float4), n4 = n/4
// ---------------------------------------------------------------------------
__global__ void round_kernel(const float* __restrict__ src, float* __restrict__ dst,
                             int n4) {
    int i = blockIdx.x * blockDim.x + threadIdx.x;
    if (i < n4) ((float4*)dst)[i] = tf32r4(((const float4*)src)[i]);
}

// ---------------------------------------------------------------------------
// cond_out[b,n] = ce[b,:] @ cond_w[:,n] + cond_b[n]   (exact fp32, tiny)
// ---------------------------------------------------------------------------
__global__ void cond_kernel(const float* __restrict__ ce,
                            const float* __restrict__ w,
                            const float* __restrict__ cb,
                            float* __restrict__ out) {
    int idx = blockIdx.x * blockDim.x + threadIdx.x;
    if (idx >= Bsz * Dm) return;
    int b = idx / Dm, n = idx % Dm;
    float s = 0.f;
    const float* cer = ce + b * 1536;
    #pragma unroll 4
    for (int k = 0; k < 1536; k++) s += cer[k] * w[k * Dm + n];
    out[idx] = s + cb[n];
}

// ---------------------------------------------------------------------------
// TF32 tensor-core GEMM, cp.async double-buffered. Inputs PRE-ROUNDED to tf32.
// C[M,N] = A[M,K] @ B[K,N] (+bias +cond +gelu +res)
// Tiles 128x128x32, 256 threads = 8 warps (4m x 2n), 2 blocks/SM.
// ---------------------------------------------------------------------------
#define TBM 128
#define TBN 128
#define TBK 32
#define ASTR 36
#define BSTR 132
#define ABUF (128 * ASTR)
#define BBUF (32 * BSTR)
#define GEMM_DSMEM (2 * (ABUF + BBUF) * 4)   // 70656 bytes

template<bool BIAS, bool GELU_F, bool RES, bool COND>
__global__ __launch_bounds__(256, 2)
void mma_gemm(const float* __restrict__ A, const float* __restrict__ Bm,
              const float* __restrict__ bias, const float* __restrict__ res,
              const float* __restrict__ cond, float* __restrict__ C,
              int M, int N, int K) {
    extern __shared__ float dsm[];
    float* AsB = dsm;
    float* BsB = dsm + 2 * ABUF;
    const uint32_t aS = (uint32_t)__cvta_generic_to_shared(AsB);
    const uint32_t bS = (uint32_t)__cvta_generic_to_shared(BsB);

    const int tid  = threadIdx.x;
    const int bm   = blockIdx.y * TBM;
    const int bn   = blockIdx.x * TBN;
    const int warp = tid >> 5, lane = tid & 31;
    const int wm = warp >> 1, wn = warp & 1;
    const int gid = lane >> 2, tig = lane & 3;
    const int m_base = wm * 32, n_base = wn * 64;

    const int ar = tid >> 3;
    const int ac = (tid & 7) * 4;
    const int br = tid >> 3;
    const int bc = (tid & 7) * 16;

    float acc[2][8][4];
    #pragma unroll
    for (int mt = 0; mt < 2; mt++)
        #pragma unroll
        for (int nt = 0; nt < 8; nt++)
            #pragma unroll
            for (int i = 0; i < 4; i++) acc[mt][nt][i] = 0.f;

    const int nk = K / TBK;

    {
        #pragma unroll
        for (int i = 0; i < 4; i++)
            cp16(aS + (uint32_t)((ar + i * 32) * ASTR + ac) * 4,
                 &A[(size_t)(bm + ar + i * 32) * K + ac]);
        #pragma unroll
        for (int i = 0; i < 4; i++)
            cp16(bS + (uint32_t)(br * BSTR + bc + i * 4) * 4,
                 &Bm[(size_t)br * N + bn + bc + i * 4]);
        CP_COMMIT();
    }

    for (int kc = 0; kc < nk; kc++) {
        const int cur = kc & 1;
        if (kc + 1 < nk) {
            const int k0 = (kc + 1) * TBK;
            uint32_t ab = aS + (uint32_t)((cur ^ 1) * ABUF) * 4;
            uint32_t bb = bS + (uint32_t)((cur ^ 1) * BBUF) * 4;
            #pragma unroll
            for (int i = 0; i < 4; i++)
                cp16(ab + (uint32_t)((ar + i * 32) * ASTR + ac) * 4,
                     &A[(size_t)(bm + ar + i * 32) * K + k0 + ac]);
            #pragma unroll
            for (int i = 0; i < 4; i++)
                cp16(bb + (uint32_t)(br * BSTR + bc + i * 4) * 4,
                     &Bm[(size_t)(k0 + br) * N + bn + bc + i * 4]);
            CP_COMMIT();
            CP_WAIT1();
        } else {
            CP_WAIT0();
        }
        __syncthreads();

        const float* As = AsB + cur * ABUF;
        const float* Bs = BsB + cur * BBUF;
        #pragma unroll
        for (int ks = 0; ks < 4; ks++) {
            const int kk = ks * 8;
            float af[2][4], bf[8][2];
            #pragma unroll
            for (int mt = 0; mt < 2; mt++) {
                int r0 = m_base + mt * 16 + gid;
                af[mt][0] = As[r0 * ASTR + kk + tig];
                af[mt][1] = As[(r0 + 8) * ASTR + kk + tig];
                af[mt][2] = As[r0 * ASTR + kk + tig + 4];
                af[mt][3] = As[(r0 + 8) * ASTR + kk + tig + 4];
            }
            #pragma unroll
            for (int nt = 0; nt < 8; nt++) {
                int c0 = n_base + nt * 8 + gid;
                bf[nt][0] = Bs[(kk + tig) * BSTR + c0];
                bf[nt][1] = Bs[(kk + tig + 4) * BSTR + c0];
            }
            #pragma unroll
            for (int mt = 0; mt < 2; mt++)
                #pragma unroll
                for (int nt = 0; nt < 8; nt++)
                    mma_tf32(acc[mt][nt], af[mt], bf[nt]);
        }
        __syncthreads();
    }

    #pragma unroll
    for (int mt = 0; mt < 2; mt++) {
        #pragma unroll
        for (int nt = 0; nt < 8; nt++) {
            int col = bn + n_base + nt * 8 + tig * 2;
            #pragma unroll
            for (int half = 0; half < 2; half++) {
                int row = bm + m_base + mt * 16 + gid + half * 8;
                float vx = acc[mt][nt][half * 2 + 0];
                float vy = acc[mt][nt][half * 2 + 1];
                if (BIAS) { vx += bias[col]; vy += bias[col + 1]; }
                if (COND) {
                    const float* cp = cond + (row >> 10) * N + col;
                    vx += cp[0]; vy += cp[1];
                }
                if (GELU_F) {
                    vx = 0.5f * vx * (1.f + erff(vx * 0.70710678118654752f));
                    vy = 0.5f * vy * (1.f + erff(vy * 0.70710678118654752f));
                    vx = tf32r(vx); vy = tf32r(vy);
                }
                if (RES) {
                    float2 rr = *(const float2*)&res[(size_t)row * N + col];
                    vx += rr.x; vy += rr.y;
                }
                float2 out = make_float2(vx, vy);
                *(float2*)&C[(size_t)row * N + col] = out;
            }
        }
    }
}

// ---------------------------------------------------------------------------
// LayerNorm: one block per token row; output rounded to tf32 (GEMM-A only).
// ---------------------------------------------------------------------------
__global__ __launch_bounds__(256)
void layernorm_kernel(const float* __restrict__ x, const float* __restrict__ g,
                      const float* __restrict__ b, float* __restrict__ out) {
    int row = blockIdx.x;
    int t = threadIdx.x;
    const float* xr = x + (size_t)row * Dm;
    float v0 = xr[t], v1 = xr[t + 256], v2 = xr[t + 512];
    float s = v0 + v1 + v2;
    float q = v0 * v0 + v1 * v1 + v2 * v2;
    #pragma unroll
    for (int o = 16; o > 0; o >>= 1) {
        s += __shfl_xor_sync(0xffffffffu, s, o);
        q += __shfl_xor_sync(0xffffffffu, q, o);
    }
    __shared__ float ss[8], sq[8];
    int wid = t >> 5, lane = t & 31;
    if (!lane) { ss[wid] = s; sq[wid] = q; }
    __syncthreads();
    if (t == 0) {
        float S = 0.f, Q = 0.f;
        #pragma unroll
        for (int i = 0; i < 8; i++) { S += ss[i]; Q += sq[i]; }
        float m = S * (1.f / Dm);
        float var = Q * (1.f / Dm) - m * m;
        ss[0] = m;
        sq[0] = rsqrtf(var + 1e-5f);
    }
    __syncthreads();
    float m = ss[0], r = sq[0];
    float* orow = out + (size_t)row * Dm;
    orow[t]       = tf32r((v0 - m) * r * g[t]       + b[t]);
    orow[t + 256] = tf32r((v1 - m) * r * g[t + 256] + b[t + 256]);
    orow[t + 512] = tf32r((v2 - m) * r * g[t + 512] + b[t + 512]);
}

// ---------------------------------------------------------------------------
// Fused RMSNorm + RoPE on q,k (rounded outputs) + round v in place.
// fp64 transcendentals (fast-math-proof; proven pass).
// ---------------------------------------------------------------------------
__global__ __launch_bounds__(768)
void rmsrope_kernel(float* __restrict__ qkv,
                    const float* __restrict__ qs,
                    const float* __restrict__ ks) {
    int token = blockIdx.x;
    int w = threadIdx.x >> 5;
    int lane = threadIdx.x & 31;
    int isK = (w >= NHn);
    int h = isK ? w - NHn : w;
    float* base = qkv + (size_t)token * (3 * Dm) + (isK ? Dm : 0) + h * HDd;
    const float* sc = isK ? ks : qs;

    float x0 = base[2 * lane], x1 = base[2 * lane + 1];
    float s = x0 * x0 + x1 * x1;
    #pragma unroll
    for (int o = 16; o > 0; o >>= 1) s += __shfl_xor_sync(0xffffffffu, s, o);
    float r = rsqrtf(s * (1.f / HDd) + 1e-6f);
    float y0 = x0 * r * sc[2 * lane];
    float y1 = x1 * r * sc[2 * lane + 1];

    int l = token & (Lseq - 1);
    int col = l & 31, rowp = l >> 5;
    double pos, fidx;
    if (lane < 16) { pos = (double)col;  fidx = (double)lane; }
    else           { pos = (double)rowp; fidx = (double)(lane - 16); }
    double omega = exp(fidx * -0.5756462732485115);
    double ang = pos * omega;
    float c  = (float)cos(ang);
    float sn = (float)sin(ang);
    base[2 * lane]     = tf32r(c * y0 - sn * y1);
    base[2 * lane + 1] = tf32r(sn * y0 + c * y1);

    float* vb = qkv + (size_t)token * (3 * Dm) + 2 * Dm;
    vb[threadIdx.x] = tf32r(vb[threadIdx.x]);
}

// ---------------------------------------------------------------------------
// Fused flash attention (FA2 warp layout). Grid (L/128, NBH), 256 thr = 8 warps.
// Warp owns 16 q-rows x ALL keys -> softmax stats warp-local (shfl over quad).
// S tile in registers; P -> PV A-fragments via quad shuffle transpose.
// K: reg-prefetch + transposed SMEM store [d][key]; V: double-buffered cp.async.
// Numerics: score = dot*0.125 + bias; m = true running max; p = tf32r(__expf);
// O = (sum p*v)/l, rounded (feeds proj GEMM).
// ---------------------------------------------------------------------------
#define FLQ 128
#define FLK 64
#define QSTR 68
#define KSTR 68
#define VSTR 68
#define KOFF (FLQ * QSTR)                 // 8704 floats
#define VOFF (KOFF + 2 * FLK * KSTR)      // 17408 floats
#define FL_DSMEM ((VOFF + 2 * FLK * VSTR) * 4)   // 104448 bytes

__global__ __launch_bounds__(256, 2)
void flash_mma(const float* __restrict__ qkv, const float* __restrict__ dens,
               const float* __restrict__ dscale, const float* __restrict__ dbias,
               int layer, float* __restrict__ o) {
    extern __shared__ float dsm[];
    float* Qs = dsm;
    float* Ks = dsm + KOFF;
    float* Vs = dsm + VOFF;
    const uint32_t qS = (uint32_t)__cvta_generic_to_shared(Qs);
    const uint32_t vS = (uint32_t)__cvta_generic_to_shared(Vs);

    const int tid = threadIdx.x;
    const int ml  = blockIdx.x * FLQ;
    const int z   = blockIdx.y;
    const int b = z / NHn, h = z % NHn;
    const int warp = tid >> 5, lane = tid & 31;
    const int gid = lane >> 2, tig = lane & 3;
    const int wRow = warp * 16;

    const float* Qb = qkv + (size_t)(b * Lseq + ml) * (3 * Dm) + h * HDd;
    const float* Kb = qkv + (size_t)(b * Lseq) * (3 * Dm) + Dm + h * HDd;
    const float* Vb = Kb + Dm;

    // stage Q (once)
    {
        int r = tid >> 1, cb = (tid & 1) * 32;
        #pragma unroll
        for (int i = 0; i < 8; i++)
            cp16(qS + (uint32_t)(r * QSTR + cb + i * 4) * 4,
                 Qb + (size_t)r * (3 * Dm) + cb + i * 4);
    }
    // K(0) -> regs; V(0) -> cp.async buf 0
    const int kkey = tid >> 2;
    const int kdb  = (tid & 3) * 4;
    float4 kr[4];
    #pragma unroll
    for (int i = 0; i < 4; i++)
        kr[i] = *(const float4*)&Kb[(size_t)kkey * (3 * Dm) + kdb + i * 16];
    const int vr = tid >> 2, vcb = (tid & 3) * 16;
    #pragma unroll
    for (int i = 0; i < 4; i++)
        cp16(vS + (uint32_t)(vr * VSTR + vcb + i * 4) * 4,
             Vb + (size_t)vr * (3 * Dm) + vcb + i * 4);
    CP_COMMIT();   // group: Q + V0

    const int r0g = ml + wRow + gid;
    const float dsc = dscale[layer], dbi = dbias[layer];
    const float bv0 = dsc * dens[b * Lseq + r0g] + dbi;
    const float bv1 = dsc * dens[b * Lseq + r0g + 8] + dbi;
    float m0 = -1e30f, m1 = -1e30f, l0 = 0.f, l1 = 0.f;

    float oacc[8][4];
    #pragma unroll
    for (int nt = 0; nt < 8; nt++)
        #pragma unroll
        for (int i = 0; i < 4; i++) oacc[nt][i] = 0.f;

    const int ntile = Lseq / FLK;   // 16
    for (int kt = 0; kt < ntile; kt++) {
        const int cur = kt & 1;
        float* Kc = Ks + cur * (FLK * KSTR);
        const float* Vc = Vs + cur * (FLK * VSTR);

        // scatter K regs -> Ks[cur] transposed [d][key]
        #pragma unroll
        for (int i = 0; i < 4; i++) {
            int d0 = kdb + i * 16;
            Kc[(d0 + 0) * KSTR + kkey] = kr[i].x;
            Kc[(d0 + 1) * KSTR + kkey] = kr[i].y;
            Kc[(d0 + 2) * KSTR + kkey] = kr[i].z;
            Kc[(d0 + 3) * KSTR + kkey] = kr[i].w;
        }
        if (kt + 1 < ntile) {
            const int kg = (kt + 1) * FLK;
            #pragma unroll
            for (int i = 0; i < 4; i++)
                kr[i] = *(const float4*)&Kb[(size_t)(kg + kkey) * (3 * Dm) + kdb + i * 16];
            uint32_t vb2 = vS + (uint32_t)((cur ^ 1) * FLK * VSTR) * 4;
            #pragma unroll
            for (int i = 0; i < 4; i++)
                cp16(vb2 + (uint32_t)(vr * VSTR + vcb + i * 4) * 4,
                     Vb + (size_t)(kg + vr) * (3 * Dm) + vcb + i * 4);
            CP_COMMIT();
            CP_WAIT1();
        } else {
            CP_WAIT0();
        }
        __syncthreads();

        // S = Q . K^T  (m16 x n64 per warp, k=64)
        float sacc[8][4];
        #pragma unroll
        for (int nt = 0; nt < 8; nt++)
            #pragma unroll
            for (int i = 0; i < 4; i++) sacc[nt][i] = 0.f;

        #pragma unroll
        for (int kkc = 0; kkc < 8; kkc++) {
            const int kk = kkc * 8;
            float aq[4];
            aq[0] = Qs[(wRow + gid) * QSTR + kk + tig];
            aq[1] = Qs[(wRow + gid + 8) * QSTR + kk + tig];
            aq[2] = Qs[(wRow + gid) * QSTR + kk + tig + 4];
            aq[3] = Qs[(wRow + gid + 8) * QSTR + kk + tig + 4];
            #pragma unroll
            for (int nt = 0; nt < 8; nt++) {
                float bf[2];
                bf[0] = Kc[(kk + tig) * KSTR + nt * 8 + gid];
                bf[1] = Kc[(kk + tig + 4) * KSTR + nt * 8 + gid];
                mma_tf32(sacc[nt], aq, bf);
            }
        }

        // scale + bias, tile row max (warp-local over quad)
        float tm0 = -1e30f, tm1 = -1e30f;
        #pragma unroll
        for (int nt = 0; nt < 8; nt++) {
            sacc[nt][0] = sacc[nt][0] * 0.125f + bv0;
            sacc[nt][1] = sacc[nt][1] * 0.125f + bv0;
            sacc[nt][2] = sacc[nt][2] * 0.125f + bv1;
            sacc[nt][3] = sacc[nt][3] * 0.125f + bv1;
            tm0 = fmaxf(tm0, fmaxf(sacc[nt][0], sacc[nt][1]));
            tm1 = fmaxf(tm1, fmaxf(sacc[nt][2], sacc[nt][3]));
        }
        tm0 = fmaxf(tm0, __shfl_xor_sync(0xffffffffu, tm0, 1));
        tm0 = fmaxf(tm0, __shfl_xor_sync(0xffffffffu, tm0, 2));
        tm1 = fmaxf(tm1, __shfl_xor_sync(0xffffffffu, tm1, 1));
        tm1 = fmaxf(tm1, __shfl_xor_sync(0xffffffffu, tm1, 2));

        const float mn0 = fmaxf(m0, tm0), mn1 = fmaxf(m1, tm1);
        const float sc0 = __expf(m0 - mn0), sc1 = __expf(m1 - mn1);
        float ps0 = 0.f, ps1 = 0.f;
        #pragma unroll
        for (int nt = 0; nt < 8; nt++) {
            float p0 = __expf(sacc[nt][0] - mn0);
            float p1 = __expf(sacc[nt][1] - mn0);
            float p2 = __expf(sacc[nt][2] - mn1);
            float p3 = __expf(sacc[nt][3] - mn1);
            ps0 += p0 + p1; ps1 += p2 + p3;
            sacc[nt][0] = tf32r(p0); sacc[nt][1] = tf32r(p1);
            sacc[nt][2] = tf32r(p2); sacc[nt][3] = tf32r(p3);
            oacc[nt][0] *= sc0; oacc[nt][1] *= sc0;
            oacc[nt][2] *= sc1; oacc[nt][3] *= sc1;
        }
        ps0 += __shfl_xor_sync(0xffffffffu, ps0, 1);
        ps0 += __shfl_xor_sync(0xffffffffu, ps0, 2);
        ps1 += __shfl_xor_sync(0xffffffffu, ps1, 1);
        ps1 += __shfl_xor_sync(0xffffffffu, ps1, 2);
        l0 = l0 * sc0 + ps0; l1 = l1 * sc1 + ps1;
        m0 = mn0; m1 = mn1;

        // PV: O += P . V   (A-frags from S-regs via quad shuffle transpose)
        const int s1l = (lane & ~3) + (tig >> 1);
        const int s2l = s1l + 2;
        const bool odd = (tig & 1);
        #pragma unroll
        for (int snt = 0; snt < 8; snt++) {
            float v00 = __shfl_sync(0xffffffffu, sacc[snt][0], s1l);
            float v01 = __shfl_sync(0xffffffffu, sacc[snt][1], s1l);
            float v20 = __shfl_sync(0xffffffffu, sacc[snt][2], s1l);
            float v21 = __shfl_sync(0xffffffffu, sacc[snt][3], s1l);
            float w00 = __shfl_sync(0xffffffffu, sacc[snt][0], s2l);
            float w01 = __shfl_sync(0xffffffffu, sacc[snt][1], s2l);
            float w20 = __shfl_sync(0xffffffffu, sacc[snt][2], s2l);
            float w21 = __shfl_sync(0xffffffffu, sacc[snt][3], s2l);
            float af[4];
            af[0] = odd ? v01 : v00;   // P[gid]  [snt*8+tig]
            af[1] = odd ? v21 : v20;   // P[gid+8][snt*8+tig]
            af[2] = odd ? w01 : w00;   // P[gid]  [snt*8+tig+4]
            af[3] = odd ? w21 : w20;   // P[gid+8][snt*8+tig+4]
            #pragma unroll
            for (int nt = 0; nt < 8; nt++) {
                float bf[2];
                bf[0] = Vc[(snt * 8 + tig) * VSTR + nt * 8 + gid];
                bf[1] = Vc[(snt * 8 + tig + 4) * VSTR + nt * 8 + gid];
                mma_tf32(oacc[nt], af, bf);
            }
        }
        __syncthreads();
    }

    const float inv0 = 1.f / l0, inv1 = 1.f / l1;
    float* ob = o + (size_t)(b * Lseq) * Dm + h * HDd;
    #pragma unroll
    for (int nt = 0; nt < 8; nt++) {
        int col = nt * 8 + tig * 2;
        float2 o0 = make_float2(tf32r(oacc[nt][0] * inv0), tf32r(oacc[nt][1] * inv0));
        float2 o1 = make_float2(tf32r(oacc[nt][2] * inv1), tf32r(oacc[nt][3] * inv1));
        *(float2*)&ob[(size_t)r0g * Dm + col] = o0;
        *(float2*)&ob[(size_t)(r0g + 8) * Dm + col] = o1;
    }
}

// ---------------------------------------------------------------------------
// Launch sequence (graph-capturable: kernel launches only)
// ---------------------------------------------------------------------------
extern "C" void kernel_launch(void* const* d_in, const int* in_sizes, int n_in,
                              void* d_out, int out_size) {
    const float* spatial   = (const float*)d_in[0];
    const float* density   = (const float*)d_in[1];
    const float* ce        = (const float*)d_in[2];
    const float* spatial_w = (const float*)d_in[3];
    const float* spatial_b = (const float*)d_in[4];
    const float* cond_w    = (const float*)d_in[5];
    const float* cond_b    = (const float*)d_in[6];
    const float* ln1_g     = (const float*)d_in[7];
    const float* ln1_b     = (const float*)d_in[8];
    const float* qkv_w     = (const float*)d_in[9];
    const float* q_scale   = (const float*)d_in[10];
    const float* k_scale   = (const float*)d_in[11];
    const float* proj_w    = (const float*)d_in[12];
    const float* proj_b    = (const float*)d_in[13];
    const float* dscale    = (const float*)d_in[14];
    const float* dbias     = (const float*)d_in[15];
    const float* ln2_g     = (const float*)d_in[16];
    const float* ln2_b     = (const float*)d_in[17];
    const float* mlp_w1    = (const float*)d_in[18];
    const float* mlp_b1    = (const float*)d_in[19];
    const float* mlp_w2    = (const float*)d_in[20];
    const float* mlp_b2    = (const float*)d_in[21];
    const float* out_w     = (const float*)d_in[22];
    const float* out_b     = (const float*)d_in[23];

    float *x, *h, *qkv, *o, *mlp, *cond;
    float *wspat, *wqkv, *wproj, *wm1, *wm2, *wout;
    cudaGetSymbolAddress((void**)&x,      g_x);
    cudaGetSymbolAddress((void**)&h,      g_h);
    cudaGetSymbolAddress((void**)&qkv,    g_qkv);
    cudaGetSymbolAddress((void**)&o,      g_o);
    cudaGetSymbolAddress((void**)&mlp,    g_mlp);
    cudaGetSymbolAddress((void**)&cond,   g_cond);
    cudaGetSymbolAddress((void**)&wspat,  g_wspat);
    cudaGetSymbolAddress((void**)&wqkv,   g_wqkv);
    cudaGetSymbolAddress((void**)&wproj,  g_wproj);
    cudaGetSymbolAddress((void**)&wm1,    g_wm1);
    cudaGetSymbolAddress((void**)&wm2,    g_wm2);
    cudaGetSymbolAddress((void**)&wout,   g_wout);

    cudaFuncSetAttribute(mma_gemm<true,  false, false, true >, cudaFuncAttributeMaxDynamicSharedMemorySize, GEMM_DSMEM);
    cudaFuncSetAttribute(mma_gemm<false, false, false, false>, cudaFuncAttributeMaxDynamicSharedMemorySize, GEMM_DSMEM);
    cudaFuncSetAttribute(mma_gemm<true,  false, true,  false>, cudaFuncAttributeMaxDynamicSharedMemorySize, GEMM_DSMEM);
    cudaFuncSetAttribute(mma_gemm<true,  true,  false, false>, cudaFuncAttributeMaxDynamicSharedMemorySize, GEMM_DSMEM);
    cudaFuncSetAttribute(mma_gemm<true,  false, false, false>, cudaFuncAttributeMaxDynamicSharedMemorySize, GEMM_DSMEM);
    cudaFuncSetAttribute(flash_mma, cudaFuncAttributeMaxDynamicSharedMemorySize, FL_DSMEM);

    // pre-round weights + spatial input (elementwise, position-independent)
    round_kernel<<<(Dm * Dm / 4 + 255) / 256, 256>>>(spatial_w, wspat, Dm * Dm / 4);
    round_kernel<<<(NLn * Dm * 3 * Dm / 4 + 255) / 256, 256>>>(qkv_w, wqkv, NLn * Dm * 3 * Dm / 4);
    round_kernel<<<(NLn * Dm * Dm / 4 + 255) / 256, 256>>>(proj_w, wproj, NLn * Dm * Dm / 4);
    round_kernel<<<(NLn * Dm * MLPd / 4 + 255) / 256, 256>>>(mlp_w1, wm1, NLn * Dm * MLPd / 4);
    round_kernel<<<(NLn * MLPd * Dm / 4 + 255) / 256, 256>>>(mlp_w2, wm2, NLn * MLPd * Dm / 4);
    round_kernel<<<(Dm * Dm / 4 + 255) / 256, 256>>>(out_w, wout, Dm * Dm / 4);
    round_kernel<<<(NTOK * Dm / 4 + 255) / 256, 256>>>(spatial, mlp, NTOK * Dm / 4);

    cond_kernel<<<(Bsz * Dm + 255) / 256, 256>>>(ce, cond_w, cond_b, cond);
    mma_gemm<true, false, false, true>
        <<<dim3(Dm / TBN, NTOK / TBM), 256, GEMM_DSMEM>>>(
        mlp, wspat, spatial_b, nullptr, cond, x, NTOK, Dm, Dm);

    for (int i = 0; i < NLn; i++) {
        layernorm_kernel<<<NTOK, 256>>>(x, ln1_g + i * Dm, ln1_b + i * Dm, h);

        mma_gemm<false, false, false, false>
            <<<dim3(3 * Dm / TBN, NTOK / TBM), 256, GEMM_DSMEM>>>(
            h, wqkv + (size_t)i * Dm * 3 * Dm, nullptr, nullptr, nullptr,
            qkv, NTOK, 3 * Dm, Dm);

        rmsrope_kernel<<<NTOK, 768>>>(qkv, q_scale + i * HDd, k_scale + i * HDd);

        flash_mma<<<dim3(Lseq / FLQ, NBH), 256, FL_DSMEM>>>(
            qkv, density, dscale, dbias, i, o);

        mma_gemm<true, false, true, false>
            <<<dim3(Dm / TBN, NTOK / TBM), 256, GEMM_DSMEM>>>(
            o, wproj + (size_t)i * Dm * Dm, proj_b + i * Dm, x, nullptr,
            x, NTOK, Dm, Dm);

        layernorm_kernel<<<NTOK, 256>>>(x, ln2_g + i * Dm, ln2_b + i * Dm, h);

        mma_gemm<true, true, false, false>
            <<<dim3(MLPd / TBN, NTOK / TBM), 256, GEMM_DSMEM>>>(
            h, wm1 + (size_t)i * Dm * MLPd, mlp_b1 + i * MLPd, nullptr,
            nullptr, mlp, NTOK, MLPd, Dm);

        mma_gemm<true, false, true, false>
            <<<dim3(Dm / TBN, NTOK / TBM), 256, GEMM_DSMEM>>>(
            mlp, wm2 + (size_t)i * MLPd * Dm, mlp_b2 + i * Dm, x, nullptr,
            x, NTOK, Dm, MLPd);
    }

    // rounded copy of x for the final GEMM (x itself stays exact)
    round_kernel<<<(NTOK * Dm / 4 + 255) / 256, 256>>>(x, h, NTOK * Dm / 4);
    mma_gemm<true, false, false, false>
        <<<dim3(Dm / TBN, NTOK / TBM), 256, GEMM_DSMEM>>>(
        h, wout, out_b, nullptr, nullptr, (float*)d_out, NTOK, Dm, Dm);
}